// round 11
// baseline (speedup 1.0000x reference)
#include <cuda_runtime.h>
#include <math.h>

#define NCAND 65536
#define NPTS  1024
#define DIM   256
#define NSPLIT 32
#define SPLIT (NCAND / NSPLIT)   // 2048
#define GSIZE 8                  // points per group (warp per point)
#define NGROUP (NPTS / GSIZE)    // 128
#define NTILES (NGROUP * NSPLIT) // 4096

// ---- scratch (__device__ globals; no allocation allowed) ----
__device__ float  g_WkT[DIM * DIM];    // WkT[j,d] = Wk[d,j]
__device__ float  g_q[NPTS * DIM];     // q = pf @ Wq + bq
__device__ float  g_t[NPTS * DIM];     // t = q @ WkT
__device__ float  g_beta[NPTS];        // q . bk
__device__ float4 g_cand[NCAND];       // (xs, ys, wc, 0)
__device__ int    g_perm[NPTS];        // morton-sorted point order
__device__ int    g_ctr;               // work-stealing counter
__device__ float  g_ps[NPTS * NSPLIT];                    // partial weight sums
__device__ float  g_pacc[(size_t)NPTS * NSPLIT * DIM];    // partial accumulators

// ---- packed f32x2 helpers ----
__device__ __forceinline__ unsigned long long ffma2(unsigned long long a,
                                                    unsigned long long b,
                                                    unsigned long long c) {
    unsigned long long d;
    asm("fma.rn.f32x2 %0, %1, %2, %3;" : "=l"(d) : "l"(a), "l"(b), "l"(c));
    return d;
}
#define UNPACK2(lo, hi, v) asm("mov.b64 {%0, %1}, %2;" : "=f"(lo), "=f"(hi) : "l"(v))
#define PACK2(v, lo, hi)   asm("mov.b64 %0, {%1, %2};" : "=l"(v) : "f"(lo), "f"(hi))

// ---------- L0: ctr reset + transpose Wk (0..63) + cand prep (64..319) + sort (320) ----------
__global__ void __launch_bounds__(256)
k_pre(const float* __restrict__ Wk,
      const float* __restrict__ centers,
      const float* __restrict__ scales,
      const float* __restrict__ boxes) {
    int bx = blockIdx.x, t = threadIdx.x;
    if (bx == 0 && t == 0) g_ctr = 0;
    if (bx < 64) {
        __shared__ float tl[32][33];
        int bi = bx & 7, bj = bx >> 3;
        int tx = t & 31, ty = t >> 5;
        #pragma unroll
        for (int r = 0; r < 4; r++)
            tl[ty + 8 * r][tx] = Wk[(bj * 32 + ty + 8 * r) * DIM + bi * 32 + tx];
        __syncthreads();
        #pragma unroll
        for (int r = 0; r < 4; r++)
            g_WkT[(bi * 32 + ty + 8 * r) * DIM + bj * 32 + tx] = tl[tx][ty + 8 * r];
    } else if (bx < 320) {
        int c = (bx - 64) * 256 + t;
        float4 ct = reinterpret_cast<const float4*>(centers)[c];
        float s = ct.z;
        float half = s * 0.5f;               // stride is exact power of 2
        int lvl = ((__float_as_int(s) >> 23) & 255) - 127 - 3;
        g_cand[c] = make_float4(ct.y + half, ct.x + half, scales[lvl], 0.f);
    } else {
        // morton bitonic sort (256 threads, 4 items each), stable via idx-in-key
        __shared__ unsigned keys[NPTS];
        #pragma unroll
        for (int m = 0; m < 4; m++) {
            int i = m * 256 + t;
            float cx = 0.5f * (boxes[i * 4 + 0] + boxes[i * 4 + 2]);
            float cy = 0.5f * (boxes[i * 4 + 1] + boxes[i * 4 + 3]);
            unsigned kx = min(255u, (unsigned)(fmaxf(cx, 0.f) * 0.25f));
            unsigned ky = min(255u, (unsigned)(fmaxf(cy, 0.f) * 0.25f));
            unsigned mo = 0;
            #pragma unroll
            for (int b = 0; b < 8; b++)
                mo |= (((kx >> b) & 1u) << (2 * b)) | (((ky >> b) & 1u) << (2 * b + 1));
            keys[i] = (mo << 10) | (unsigned)i;
        }
        for (unsigned k = 2; k <= NPTS; k <<= 1) {
            for (unsigned j = k >> 1; j > 0; j >>= 1) {
                __syncthreads();
                #pragma unroll
                for (int m = 0; m < 4; m++) {
                    unsigned i = m * 256 + t;
                    unsigned ixj = i ^ j;
                    if (ixj > i) {
                        unsigned a = keys[i], b = keys[ixj];
                        bool up = ((i & k) == 0);
                        if ((a > b) == up) { keys[i] = b; keys[ixj] = a; }
                    }
                }
            }
        }
        __syncthreads();
        #pragma unroll
        for (int m = 0; m < 4; m++) {
            int i = m * 256 + t;
            g_perm[i] = (int)(keys[i] & 1023u);
        }
    }
}

// ---------- L1: q = pf @ Wq + bq (4 points per CTA) ----------
__global__ void __launch_bounds__(256)
k_q(const float* __restrict__ pf, const float* __restrict__ Wq,
    const float* __restrict__ bq) {
    __shared__ float sp[4][DIM];
    int j = threadIdx.x;
    int p0 = blockIdx.x * 4;
    #pragma unroll
    for (int k = 0; k < 4; k++) sp[k][j] = pf[(p0 + k) * DIM + j];
    __syncthreads();
    float b = bq[j];
    float acc[4] = {b, b, b, b};
    for (int e = 0; e < DIM; e += 8) {
        float a[8];
        #pragma unroll
        for (int i = 0; i < 8; i++) a[i] = Wq[(e + i) * DIM + j];
        #pragma unroll
        for (int k = 0; k < 4; k++) {
            float4 v1 = *reinterpret_cast<const float4*>(&sp[k][e]);
            float4 v2 = *reinterpret_cast<const float4*>(&sp[k][e + 4]);
            acc[k] += v1.x*a[0] + v1.y*a[1] + v1.z*a[2] + v1.w*a[3]
                    + v2.x*a[4] + v2.y*a[5] + v2.z*a[6] + v2.w*a[7];
        }
    }
    #pragma unroll
    for (int k = 0; k < 4; k++) g_q[(p0 + k) * DIM + j] = acc[k];
}

// ---------- L2: t = q @ WkT (4 points per CTA), beta = q.bk fused ----------
__global__ void __launch_bounds__(256)
k_t2(const float* __restrict__ bk) {
    __shared__ float sq[4][DIM];
    int d = threadIdx.x;
    int p0 = blockIdx.x * 4;
    #pragma unroll
    for (int k = 0; k < 4; k++) sq[k][d] = g_q[(p0 + k) * DIM + d];
    __syncthreads();

    int wid = d >> 5, lane = d & 31;
    if (wid < 4) {   // beta for p0+wid
        const float4* r4 = reinterpret_cast<const float4*>(&sq[wid][0]);
        const float4* v4 = reinterpret_cast<const float4*>(bk);
        float4 ra = r4[lane], rb = r4[lane + 32];
        float4 va = v4[lane], vb = v4[lane + 32];
        float dp = ra.x*va.x + ra.y*va.y + ra.z*va.z + ra.w*va.w +
                   rb.x*vb.x + rb.y*vb.y + rb.z*vb.z + rb.w*vb.w;
        #pragma unroll
        for (int o = 16; o > 0; o >>= 1) dp += __shfl_xor_sync(0xffffffffu, dp, o);
        if (lane == 0) g_beta[p0 + wid] = dp;
    }

    float acc[4] = {0.f, 0.f, 0.f, 0.f};
    for (int j = 0; j < DIM; j += 8) {
        float a[8];
        #pragma unroll
        for (int i = 0; i < 8; i++) a[i] = g_WkT[(j + i) * DIM + d];
        #pragma unroll
        for (int k = 0; k < 4; k++) {
            float4 v1 = *reinterpret_cast<const float4*>(&sq[k][j]);
            float4 v2 = *reinterpret_cast<const float4*>(&sq[k][j + 4]);
            acc[k] += v1.x*a[0] + v1.y*a[1] + v1.z*a[2] + v1.w*a[3]
                    + v2.x*a[4] + v2.y*a[5] + v2.z*a[6] + v2.w*a[7];
        }
    }
    #pragma unroll
    for (int k = 0; k < 4; k++) g_t[(p0 + k) * DIM + d] = acc[k];
}

// ---------- L3: persistent attention — R10 structure, FFMA2 math ----------
__global__ void __launch_bounds__(256, 4)
k_attn(const float* __restrict__ bf, const float* __restrict__ boxes) {
    __shared__ float s_xs[SPLIT];
    __shared__ float s_ys[SPLIT];
    __shared__ float s_ws[SPLIT];
    __shared__ unsigned short s_id[SPLIT];
    __shared__ unsigned short s_qq[8][32];
    __shared__ float s_t[GSIZE][DIM];
    __shared__ float4 s_bx[GSIZE];
    __shared__ float s_gbb[4];
    __shared__ int s_wcnt[8], s_woff[8];
    __shared__ int s_run, s_tile;

    int tid = threadIdx.x, wid = tid >> 5, lane = tid & 31;
    int h = lane >> 4, i = lane & 15;

    for (;;) {
        if (tid == 0) s_tile = atomicAdd(&g_ctr, 1);
        __syncthreads();
        int tile = s_tile;
        if (tile >= NTILES) return;
        int g = tile >> 5;                 // tile / NSPLIT
        int s = tile & (NSPLIT - 1);

        int p = g_perm[g * GSIZE + wid];
        if (tid < GSIZE) {
            int pp = g_perm[g * GSIZE + tid];
            s_bx[tid] = reinterpret_cast<const float4*>(boxes)[pp];
        }
        {   // stage this warp's t into smem
            const float4* t4 = reinterpret_cast<const float4*>(g_t + (size_t)p * DIM);
            float4 v0 = t4[lane], v1 = t4[lane + 32];
            reinterpret_cast<float4*>(s_t[wid])[lane] = v0;
            reinterpret_cast<float4*>(s_t[wid])[lane + 32] = v1;
        }
        if (tid == 0) s_run = 0;
        __syncthreads();
        if (tid == 0) {
            float gx1 = 1e30f, gy1 = 1e30f, gx2 = -1e30f, gy2 = -1e30f;
            #pragma unroll
            for (int k = 0; k < GSIZE; k++) {
                float4 b = s_bx[k];
                gx1 = fminf(gx1, b.x); gy1 = fminf(gy1, b.y);
                gx2 = fmaxf(gx2, b.z); gy2 = fmaxf(gy2, b.w);
            }
            s_gbb[0] = gx1; s_gbb[1] = gy1; s_gbb[2] = gx2; s_gbb[3] = gy2;
        }
        __syncthreads();
        float gx1 = s_gbb[0], gy1 = s_gbb[1], gx2 = s_gbb[2], gy2 = s_gbb[3];

        // ---- prefilter: deterministic ordered compaction into shortlist ----
        const int base = s * SPLIT;
        #pragma unroll 1
        for (int it = 0; it < SPLIT / 256; it++) {
            int c = base + it * 256 + tid;
            float4 cd = g_cand[c];
            bool hg = (cd.x > gx1) && (cd.y > gy1) && (cd.x < gx2) && (cd.y < gy2);
            unsigned bal = __ballot_sync(0xffffffffu, hg);
            if (lane == 0) s_wcnt[wid] = __popc(bal);
            __syncthreads();
            if (tid == 0) {
                int r = s_run;
                #pragma unroll
                for (int w = 0; w < 8; w++) { s_woff[w] = r; r += s_wcnt[w]; }
                s_run = r;
            }
            __syncthreads();
            if (hg) {
                int off = s_woff[wid] + __popc(bal & ((1u << lane) - 1u));
                s_xs[off] = cd.x; s_ys[off] = cd.y;
                s_ws[off] = cd.z;
                s_id[off] = (unsigned short)c;
            }
        }
        __syncthreads();
        int cnt = s_run;

        // ---- hit loop: half-warp per hit, t from smem, FFMA2 math ----
        float4 box = s_bx[wid];
        float x1 = box.x, y1 = box.y, x2 = box.z, y2 = box.w;
        float beta = g_beta[p];
        const ulonglong2* tv = reinterpret_cast<const ulonglong2*>(s_t[wid]);

        unsigned long long acc[8] = {0ull,0ull,0ull,0ull,0ull,0ull,0ull,0ull};
        float ssum = 0.f;

        for (int sl = 0; sl < cnt; sl += 32) {
            __syncwarp();
            int idx = sl + lane;
            bool valid = idx < cnt;
            float cx = s_xs[idx];   // oob-by-<32 reads land in s_ys: gated by valid
            float cy = s_ys[idx];
            bool hit = valid && (cx > x1) && (cy > y1) && (cx < x2) && (cy < y2);
            unsigned bal = __ballot_sync(0xffffffffu, hit);
            int nh = __popc(bal);
            if (hit) s_qq[wid][__popc(bal & ((1u << lane) - 1u))] = (unsigned short)idx;
            __syncwarp();
            for (int j = 0; j < nh; j += 2) {
                int qi = j + h;                 // half h processes hit j+h
                bool v = qi < nh;
                int pos = s_qq[wid][v ? qi : 0];
                int ch = s_id[pos];
                float wc = s_ws[pos];
                const ulonglong2* r = reinterpret_cast<const ulonglong2*>(bf + (size_t)ch * DIM);
                ulonglong2 r0 = r[i], r1 = r[i + 16], r2 = r[i + 32], r3 = r[i + 48];
                ulonglong2 t0 = tv[i], t1 = tv[i + 16], t2 = tv[i + 32], t3 = tv[i + 48];
                unsigned long long cA = 0ull, cB = 0ull;
                cA = ffma2(r0.x, t0.x, cA); cA = ffma2(r0.y, t0.y, cA);
                cA = ffma2(r1.x, t1.x, cA); cA = ffma2(r1.y, t1.y, cA);
                cB = ffma2(r2.x, t2.x, cB); cB = ffma2(r2.y, t2.y, cB);
                cB = ffma2(r3.x, t3.x, cB); cB = ffma2(r3.y, t3.y, cB);
                float la, ha, lb, hb;
                UNPACK2(la, ha, cA);
                UNPACK2(lb, hb, cB);
                float dp = (la + lb) + (ha + hb);
                dp += __shfl_xor_sync(0xffffffffu, dp, 8);
                dp += __shfl_xor_sync(0xffffffffu, dp, 4);
                dp += __shfl_xor_sync(0xffffffffu, dp, 2);
                dp += __shfl_xor_sync(0xffffffffu, dp, 1);
                float logit = fminf(fmaxf(wc * dp + beta, -50.f), 50.f);
                // logits clipped to <=50; fixed reference replaces online max
                float w = __expf(logit - 50.f);
                if (!v) w = 0.f;
                ssum += w;
                unsigned long long w2;
                PACK2(w2, w, w);
                acc[0] = ffma2(w2, r0.x, acc[0]); acc[1] = ffma2(w2, r0.y, acc[1]);
                acc[2] = ffma2(w2, r1.x, acc[2]); acc[3] = ffma2(w2, r1.y, acc[3]);
                acc[4] = ffma2(w2, r2.x, acc[4]); acc[5] = ffma2(w2, r2.y, acc[5]);
                acc[6] = ffma2(w2, r3.x, acc[6]); acc[7] = ffma2(w2, r3.y, acc[7]);
            }
        }

        // unpack accumulators, cross-half combine
        float av[16];
        #pragma unroll
        for (int k = 0; k < 8; k++) UNPACK2(av[2 * k], av[2 * k + 1], acc[k]);
        ssum += __shfl_xor_sync(0xffffffffu, ssum, 16);
        #pragma unroll
        for (int k = 0; k < 16; k++) av[k] += __shfl_xor_sync(0xffffffffu, av[k], 16);

        int slot = p * NSPLIT + s;
        if (h == 0) {
            float4* pa = reinterpret_cast<float4*>(g_pacc + (size_t)slot * DIM);
            pa[i]      = make_float4(av[0],  av[1],  av[2],  av[3]);
            pa[i + 16] = make_float4(av[4],  av[5],  av[6],  av[7]);
            pa[i + 32] = make_float4(av[8],  av[9],  av[10], av[11]);
            pa[i + 48] = make_float4(av[12], av[13], av[14], av[15]);
        }
        if (lane == 0) g_ps[slot] = ssum;
        __syncthreads();   // protect smem before next tile
    }
}

// ---------- L4: combine partials + residual ----------
__global__ void __launch_bounds__(256) k_combine(const float* __restrict__ pf,
                                                 float* __restrict__ out) {
    int p = blockIdx.x;
    int d = threadIdx.x;
    float num = 0.f, den = 0.f;
    #pragma unroll 8
    for (int s = 0; s < NSPLIT; s++) {
        den += g_ps[p * NSPLIT + s];
        num += g_pacc[(size_t)(p * NSPLIT + s) * DIM + d];
    }
    float merge = (den > 0.f) ? (num / den) : 0.f;
    out[p * DIM + d] = pf[p * DIM + d] + merge;
}

extern "C" void kernel_launch(void* const* d_in, const int* in_sizes, int n_in,
                              void* d_out, int out_size) {
    const float* points_feat = (const float*)d_in[0];
    const float* box_feat    = (const float*)d_in[1];
    const float* centers     = (const float*)d_in[2];
    const float* boxes       = (const float*)d_in[3];
    const float* Wq          = (const float*)d_in[4];
    const float* bq          = (const float*)d_in[5];
    const float* Wk          = (const float*)d_in[6];
    const float* bk          = (const float*)d_in[7];
    const float* scales      = (const float*)d_in[8];
    float* out = (float*)d_out;

    k_pre<<<321, 256>>>(Wk, centers, scales, boxes);   // launch 0
    k_q<<<NPTS / 4, 256>>>(points_feat, Wq, bq);       // launch 1
    k_t2<<<NPTS / 4, 256>>>(bk);                       // launch 2
    k_attn<<<592, 256>>>(box_feat, boxes);             // launch 3 (ncu target)
    k_combine<<<NPTS, 256>>>(points_feat, out);        // launch 4
}

// round 12
// speedup vs baseline: 1.0463x; 1.0463x over previous
#include <cuda_runtime.h>
#include <math.h>

#define NCAND 65536
#define NPTS  1024
#define DIM   256
#define NSPLIT 32
#define SPLIT (NCAND / NSPLIT)   // 2048
#define GSIZE 16                 // points per group (warp per point, 16 warps)
#define NGROUP (NPTS / GSIZE)    // 64
#define NTILES (NGROUP * NSPLIT) // 2048
#define ATHR 512                 // k_attn block size

// ---- scratch (__device__ globals; no allocation allowed) ----
__device__ float  g_WkT[DIM * DIM];    // WkT[j,d] = Wk[d,j]
__device__ float  g_t[NPTS * DIM];     // t = (pf@Wq+bq) @ WkT
__device__ float  g_beta[NPTS];        // q . bk
__device__ float4 g_cand[NCAND];       // (xs, ys, wc, 0)
__device__ int    g_perm[NPTS];        // morton-sorted point order
__device__ int    g_ctr;               // work-stealing counter
__device__ float  g_ps[NPTS * NSPLIT];                    // partial weight sums
__device__ float  g_pacc[(size_t)NPTS * NSPLIT * DIM];    // partial accumulators

// ---------- L0: transpose Wk (0..63) + cand prep (64..319) + sort (320) ----------
__global__ void __launch_bounds__(256)
k_pre(const float* __restrict__ Wk,
      const float* __restrict__ centers,
      const float* __restrict__ scales,
      const float* __restrict__ boxes) {
    int bx = blockIdx.x, t = threadIdx.x;
    if (bx < 64) {
        __shared__ float tl[32][33];
        int bi = bx & 7, bj = bx >> 3;
        int tx = t & 31, ty = t >> 5;
        #pragma unroll
        for (int r = 0; r < 4; r++)
            tl[ty + 8 * r][tx] = Wk[(bj * 32 + ty + 8 * r) * DIM + bi * 32 + tx];
        __syncthreads();
        #pragma unroll
        for (int r = 0; r < 4; r++)
            g_WkT[(bi * 32 + ty + 8 * r) * DIM + bj * 32 + tx] = tl[tx][ty + 8 * r];
    } else if (bx < 320) {
        int c = (bx - 64) * 256 + t;
        float4 ct = reinterpret_cast<const float4*>(centers)[c];
        float s = ct.z;
        float half = s * 0.5f;               // stride is exact power of 2
        int lvl = ((__float_as_int(s) >> 23) & 255) - 127 - 3;
        g_cand[c] = make_float4(ct.y + half, ct.x + half, scales[lvl], 0.f);
    } else {
        // morton bitonic sort (256 threads, 4 items each), stable via idx-in-key
        __shared__ unsigned keys[NPTS];
        #pragma unroll
        for (int m = 0; m < 4; m++) {
            int i = m * 256 + t;
            float cx = 0.5f * (boxes[i * 4 + 0] + boxes[i * 4 + 2]);
            float cy = 0.5f * (boxes[i * 4 + 1] + boxes[i * 4 + 3]);
            unsigned kx = min(255u, (unsigned)(fmaxf(cx, 0.f) * 0.25f));
            unsigned ky = min(255u, (unsigned)(fmaxf(cy, 0.f) * 0.25f));
            unsigned mo = 0;
            #pragma unroll
            for (int b = 0; b < 8; b++)
                mo |= (((kx >> b) & 1u) << (2 * b)) | (((ky >> b) & 1u) << (2 * b + 1));
            keys[i] = (mo << 10) | (unsigned)i;
        }
        for (unsigned k = 2; k <= NPTS; k <<= 1) {
            for (unsigned j = k >> 1; j > 0; j >>= 1) {
                __syncthreads();
                #pragma unroll
                for (int m = 0; m < 4; m++) {
                    unsigned i = m * 256 + t;
                    unsigned ixj = i ^ j;
                    if (ixj > i) {
                        unsigned a = keys[i], b = keys[ixj];
                        bool up = ((i & k) == 0);
                        if ((a > b) == up) { keys[i] = b; keys[ixj] = a; }
                    }
                }
            }
        }
        __syncthreads();
        #pragma unroll
        for (int m = 0; m < 4; m++) {
            int i = m * 256 + t;
            g_perm[i] = (int)(keys[i] & 1023u);
        }
    }
}

// ---------- L1: fused q = pf@Wq+bq, t = q@WkT, beta = q.bk (4 points/CTA, 256 CTAs) ----------
__global__ void __launch_bounds__(256)
k_qt(const float* __restrict__ pf, const float* __restrict__ Wq,
     const float* __restrict__ bq, const float* __restrict__ bk) {
    __shared__ float sp[4][DIM];
    __shared__ float sq[4][DIM];
    int d = threadIdx.x;
    int p0 = blockIdx.x * 4;
    #pragma unroll
    for (int k = 0; k < 4; k++) sp[k][d] = pf[(p0 + k) * DIM + d];
    __syncthreads();

    {   // q phase
        float b = bq[d];
        float acc[4] = {b, b, b, b};
        for (int e = 0; e < DIM; e += 8) {
            float a[8];
            #pragma unroll
            for (int i = 0; i < 8; i++) a[i] = Wq[(e + i) * DIM + d];
            #pragma unroll
            for (int k = 0; k < 4; k++) {
                float4 v1 = *reinterpret_cast<const float4*>(&sp[k][e]);
                float4 v2 = *reinterpret_cast<const float4*>(&sp[k][e + 4]);
                acc[k] += v1.x*a[0] + v1.y*a[1] + v1.z*a[2] + v1.w*a[3]
                        + v2.x*a[4] + v2.y*a[5] + v2.z*a[6] + v2.w*a[7];
            }
        }
        #pragma unroll
        for (int k = 0; k < 4; k++) sq[k][d] = acc[k];
    }
    __syncthreads();

    int wid = d >> 5, lane = d & 31;
    if (wid < 4) {   // beta for p0+wid
        const float4* r4 = reinterpret_cast<const float4*>(&sq[wid][0]);
        const float4* v4 = reinterpret_cast<const float4*>(bk);
        float4 ra = r4[lane], rb = r4[lane + 32];
        float4 va = v4[lane], vb = v4[lane + 32];
        float dp = ra.x*va.x + ra.y*va.y + ra.z*va.z + ra.w*va.w +
                   rb.x*vb.x + rb.y*vb.y + rb.z*vb.z + rb.w*vb.w;
        #pragma unroll
        for (int o = 16; o > 0; o >>= 1) dp += __shfl_xor_sync(0xffffffffu, dp, o);
        if (lane == 0) g_beta[p0 + wid] = dp;
    }

    {   // t phase
        float acc[4] = {0.f, 0.f, 0.f, 0.f};
        for (int j = 0; j < DIM; j += 8) {
            float a[8];
            #pragma unroll
            for (int i = 0; i < 8; i++) a[i] = g_WkT[(j + i) * DIM + d];
            #pragma unroll
            for (int k = 0; k < 4; k++) {
                float4 v1 = *reinterpret_cast<const float4*>(&sq[k][j]);
                float4 v2 = *reinterpret_cast<const float4*>(&sq[k][j + 4]);
                acc[k] += v1.x*a[0] + v1.y*a[1] + v1.z*a[2] + v1.w*a[3]
                        + v2.x*a[4] + v2.y*a[5] + v2.z*a[6] + v2.w*a[7];
            }
        }
        #pragma unroll
        for (int k = 0; k < 4; k++) g_t[(p0 + k) * DIM + d] = acc[k];
    }
}

// ---------- L2: reset work-stealing counter ----------
__global__ void k_rst() { if (threadIdx.x == 0) g_ctr = 0; }

// ---------- L3: persistent attention — 16 warps/CTA, warp per point ----------
__global__ void __launch_bounds__(ATHR, 2)
k_attn(const float* __restrict__ bf, const float* __restrict__ boxes) {
    __shared__ float s_xs[SPLIT];
    __shared__ float s_ys[SPLIT];
    __shared__ float s_ws[SPLIT];
    __shared__ unsigned short s_id[SPLIT];
    __shared__ unsigned short s_qq[16][32];
    __shared__ float s_t[GSIZE][DIM];
    __shared__ float4 s_bx[GSIZE];
    __shared__ float s_gbb[4];
    __shared__ int s_wcnt[16], s_woff[16];
    __shared__ int s_run, s_tile;

    int tid = threadIdx.x, wid = tid >> 5, lane = tid & 31;
    int h = lane >> 4, i = lane & 15;

    for (;;) {
        if (tid == 0) s_tile = atomicAdd(&g_ctr, 1);
        __syncthreads();
        int tile = s_tile;
        if (tile >= NTILES) return;
        int g = tile >> 5;                 // tile / NSPLIT
        int s = tile & (NSPLIT - 1);

        int p = g_perm[g * GSIZE + wid];
        if (tid < GSIZE) {
            int pp = g_perm[g * GSIZE + tid];
            s_bx[tid] = reinterpret_cast<const float4*>(boxes)[pp];
        }
        {   // stage this warp's t into smem
            const float4* t4 = reinterpret_cast<const float4*>(g_t + (size_t)p * DIM);
            float4 v0 = t4[lane], v1 = t4[lane + 32];
            reinterpret_cast<float4*>(s_t[wid])[lane] = v0;
            reinterpret_cast<float4*>(s_t[wid])[lane + 32] = v1;
        }
        if (tid == 0) s_run = 0;
        __syncthreads();
        if (tid == 0) {
            float gx1 = 1e30f, gy1 = 1e30f, gx2 = -1e30f, gy2 = -1e30f;
            #pragma unroll
            for (int k = 0; k < GSIZE; k++) {
                float4 b = s_bx[k];
                gx1 = fminf(gx1, b.x); gy1 = fminf(gy1, b.y);
                gx2 = fmaxf(gx2, b.z); gy2 = fmaxf(gy2, b.w);
            }
            s_gbb[0] = gx1; s_gbb[1] = gy1; s_gbb[2] = gx2; s_gbb[3] = gy2;
        }
        __syncthreads();
        float gx1 = s_gbb[0], gy1 = s_gbb[1], gx2 = s_gbb[2], gy2 = s_gbb[3];

        // ---- prefilter: deterministic ordered compaction (512 threads, 4 iters) ----
        const int base = s * SPLIT;
        #pragma unroll 1
        for (int it = 0; it < SPLIT / ATHR; it++) {
            int c = base + it * ATHR + tid;
            float4 cd = g_cand[c];
            bool hg = (cd.x > gx1) && (cd.y > gy1) && (cd.x < gx2) && (cd.y < gy2);
            unsigned bal = __ballot_sync(0xffffffffu, hg);
            if (lane == 0) s_wcnt[wid] = __popc(bal);
            __syncthreads();
            if (tid == 0) {
                int r = s_run;
                #pragma unroll
                for (int w = 0; w < 16; w++) { s_woff[w] = r; r += s_wcnt[w]; }
                s_run = r;
            }
            __syncthreads();
            if (hg) {
                int off = s_woff[wid] + __popc(bal & ((1u << lane) - 1u));
                s_xs[off] = cd.x; s_ys[off] = cd.y;
                s_ws[off] = cd.z;
                s_id[off] = (unsigned short)c;
            }
        }
        __syncthreads();
        int cnt = s_run;

        // ---- hit loop: half-warp per hit, t from smem, scalar float4 FMA ----
        float4 box = s_bx[wid];
        float x1 = box.x, y1 = box.y, x2 = box.z, y2 = box.w;
        float beta = g_beta[p];
        const float4* tv = reinterpret_cast<const float4*>(s_t[wid]);

        float4 a0 = make_float4(0.f,0.f,0.f,0.f), a1 = a0, a2 = a0, a3 = a0;
        float ssum = 0.f;

        for (int sl = 0; sl < cnt; sl += 32) {
            __syncwarp();
            int idx = sl + lane;
            bool valid = idx < cnt;
            float cx = s_xs[idx];   // oob-by-<32 reads land in s_ys: gated by valid
            float cy = s_ys[idx];
            bool hit = valid && (cx > x1) && (cy > y1) && (cx < x2) && (cy < y2);
            unsigned bal = __ballot_sync(0xffffffffu, hit);
            int nh = __popc(bal);
            if (hit) s_qq[wid][__popc(bal & ((1u << lane) - 1u))] = (unsigned short)idx;
            __syncwarp();
            for (int j = 0; j < nh; j += 2) {
                int qi = j + h;                 // half h processes hit j+h
                bool v = qi < nh;
                int pos = s_qq[wid][v ? qi : 0];
                int ch = s_id[pos];
                float wc = s_ws[pos];
                const float4* r = reinterpret_cast<const float4*>(bf + (size_t)ch * DIM);
                float4 r0 = r[i], r1 = r[i + 16], r2 = r[i + 32], r3 = r[i + 48];
                float4 t0 = tv[i], t1 = tv[i + 16], t2 = tv[i + 32], t3 = tv[i + 48];
                float dp = r0.x*t0.x + r0.y*t0.y + r0.z*t0.z + r0.w*t0.w
                         + r1.x*t1.x + r1.y*t1.y + r1.z*t1.z + r1.w*t1.w
                         + r2.x*t2.x + r2.y*t2.y + r2.z*t2.z + r2.w*t2.w
                         + r3.x*t3.x + r3.y*t3.y + r3.z*t3.z + r3.w*t3.w;
                dp += __shfl_xor_sync(0xffffffffu, dp, 8);
                dp += __shfl_xor_sync(0xffffffffu, dp, 4);
                dp += __shfl_xor_sync(0xffffffffu, dp, 2);
                dp += __shfl_xor_sync(0xffffffffu, dp, 1);
                float logit = fminf(fmaxf(wc * dp + beta, -50.f), 50.f);
                // logits clipped to <=50; fixed reference replaces online max
                float w = __expf(logit - 50.f);
                if (!v) w = 0.f;
                ssum += w;
                a0.x += w*r0.x; a0.y += w*r0.y; a0.z += w*r0.z; a0.w += w*r0.w;
                a1.x += w*r1.x; a1.y += w*r1.y; a1.z += w*r1.z; a1.w += w*r1.w;
                a2.x += w*r2.x; a2.y += w*r2.y; a2.z += w*r2.z; a2.w += w*r2.w;
                a3.x += w*r3.x; a3.y += w*r3.y; a3.z += w*r3.z; a3.w += w*r3.w;
            }
        }

        // cross-half combine
        ssum += __shfl_xor_sync(0xffffffffu, ssum, 16);
        a0.x += __shfl_xor_sync(0xffffffffu, a0.x, 16);
        a0.y += __shfl_xor_sync(0xffffffffu, a0.y, 16);
        a0.z += __shfl_xor_sync(0xffffffffu, a0.z, 16);
        a0.w += __shfl_xor_sync(0xffffffffu, a0.w, 16);
        a1.x += __shfl_xor_sync(0xffffffffu, a1.x, 16);
        a1.y += __shfl_xor_sync(0xffffffffu, a1.y, 16);
        a1.z += __shfl_xor_sync(0xffffffffu, a1.z, 16);
        a1.w += __shfl_xor_sync(0xffffffffu, a1.w, 16);
        a2.x += __shfl_xor_sync(0xffffffffu, a2.x, 16);
        a2.y += __shfl_xor_sync(0xffffffffu, a2.y, 16);
        a2.z += __shfl_xor_sync(0xffffffffu, a2.z, 16);
        a2.w += __shfl_xor_sync(0xffffffffu, a2.w, 16);
        a3.x += __shfl_xor_sync(0xffffffffu, a3.x, 16);
        a3.y += __shfl_xor_sync(0xffffffffu, a3.y, 16);
        a3.z += __shfl_xor_sync(0xffffffffu, a3.z, 16);
        a3.w += __shfl_xor_sync(0xffffffffu, a3.w, 16);

        int slot = p * NSPLIT + s;
        if (h == 0) {
            float4* pa = reinterpret_cast<float4*>(g_pacc + (size_t)slot * DIM);
            pa[i] = a0; pa[i + 16] = a1; pa[i + 32] = a2; pa[i + 48] = a3;
        }
        if (lane == 0) g_ps[slot] = ssum;
        __syncthreads();   // protect smem before next tile
    }
}

// ---------- L4: combine partials + residual ----------
__global__ void __launch_bounds__(256) k_combine(const float* __restrict__ pf,
                                                 float* __restrict__ out) {
    int p = blockIdx.x;
    int d = threadIdx.x;
    float num = 0.f, den = 0.f;
    #pragma unroll 8
    for (int s = 0; s < NSPLIT; s++) {
        den += g_ps[p * NSPLIT + s];
        num += g_pacc[(size_t)(p * NSPLIT + s) * DIM + d];
    }
    float merge = (den > 0.f) ? (num / den) : 0.f;
    out[p * DIM + d] = pf[p * DIM + d] + merge;
}

extern "C" void kernel_launch(void* const* d_in, const int* in_sizes, int n_in,
                              void* d_out, int out_size) {
    const float* points_feat = (const float*)d_in[0];
    const float* box_feat    = (const float*)d_in[1];
    const float* centers     = (const float*)d_in[2];
    const float* boxes       = (const float*)d_in[3];
    const float* Wq          = (const float*)d_in[4];
    const float* bq          = (const float*)d_in[5];
    const float* Wk          = (const float*)d_in[6];
    const float* bk          = (const float*)d_in[7];
    const float* scales      = (const float*)d_in[8];
    float* out = (float*)d_out;

    k_pre<<<321, 256>>>(Wk, centers, scales, boxes);   // launch 0
    k_qt<<<NPTS / 4, 256>>>(points_feat, Wq, bq, bk);  // launch 1
    k_rst<<<1, 32>>>();                                // launch 2
    k_attn<<<296, ATHR>>>(box_feat, boxes);            // launch 3 (ncu target)
    k_combine<<<NPTS, 256>>>(points_feat, out);        // launch 4
}

// round 13
// speedup vs baseline: 1.0556x; 1.0089x over previous
#include <cuda_runtime.h>
#include <math.h>

#define NCAND 65536
#define NPTS  1024
#define DIM   256
#define NSPLIT 32
#define SPLIT (NCAND / NSPLIT)   // 2048
#define GSIZE 8                  // points per group (warp per point)
#define NGROUP (NPTS / GSIZE)    // 128

// ---- scratch (__device__ globals; no allocation allowed) ----
__device__ float  g_WkT[DIM * DIM];    // WkT[j,d] = Wk[d,j]
__device__ float  g_t[NPTS * DIM];     // t = (pf@Wq+bq) @ WkT
__device__ float  g_beta[NPTS];        // q . bk
__device__ float2 g_cxy[NCAND];        // candidate (xs, ys)
__device__ float  g_wc[NCAND];         // scales[lvl]
__device__ int    g_perm[NPTS];        // morton-sorted point order
__device__ int    g_ctr;               // (dummy-launch target)
__device__ float  g_ps[NPTS * NSPLIT];                    // partial weight sums
__device__ float  g_pacc[(size_t)NPTS * NSPLIT * DIM];    // partial accumulators

// ---------- L0: transpose Wk (0..63) + cand prep (64..319) + sort (320) ----------
__global__ void __launch_bounds__(256)
k_pre(const float* __restrict__ Wk,
      const float* __restrict__ centers,
      const float* __restrict__ scales,
      const float* __restrict__ boxes) {
    int bx = blockIdx.x, t = threadIdx.x;
    if (bx < 64) {
        __shared__ float tl[32][33];
        int bi = bx & 7, bj = bx >> 3;
        int tx = t & 31, ty = t >> 5;
        #pragma unroll
        for (int r = 0; r < 4; r++)
            tl[ty + 8 * r][tx] = Wk[(bj * 32 + ty + 8 * r) * DIM + bi * 32 + tx];
        __syncthreads();
        #pragma unroll
        for (int r = 0; r < 4; r++)
            g_WkT[(bi * 32 + ty + 8 * r) * DIM + bj * 32 + tx] = tl[tx][ty + 8 * r];
    } else if (bx < 320) {
        int c = (bx - 64) * 256 + t;
        float4 ct = reinterpret_cast<const float4*>(centers)[c];
        float s = ct.z;
        float half = s * 0.5f;               // stride is exact power of 2
        g_cxy[c] = make_float2(ct.y + half, ct.x + half);   // (xs, ys)
        int lvl = ((__float_as_int(s) >> 23) & 255) - 127 - 3;
        g_wc[c] = scales[lvl];
    } else {
        // morton bitonic sort (256 threads, 4 items each), stable via idx-in-key
        __shared__ unsigned keys[NPTS];
        #pragma unroll
        for (int m = 0; m < 4; m++) {
            int i = m * 256 + t;
            float cx = 0.5f * (boxes[i * 4 + 0] + boxes[i * 4 + 2]);
            float cy = 0.5f * (boxes[i * 4 + 1] + boxes[i * 4 + 3]);
            unsigned kx = min(255u, (unsigned)(fmaxf(cx, 0.f) * 0.25f));
            unsigned ky = min(255u, (unsigned)(fmaxf(cy, 0.f) * 0.25f));
            unsigned mo = 0;
            #pragma unroll
            for (int b = 0; b < 8; b++)
                mo |= (((kx >> b) & 1u) << (2 * b)) | (((ky >> b) & 1u) << (2 * b + 1));
            keys[i] = (mo << 10) | (unsigned)i;
        }
        for (unsigned k = 2; k <= NPTS; k <<= 1) {
            for (unsigned j = k >> 1; j > 0; j >>= 1) {
                __syncthreads();
                #pragma unroll
                for (int m = 0; m < 4; m++) {
                    unsigned i = m * 256 + t;
                    unsigned ixj = i ^ j;
                    if (ixj > i) {
                        unsigned a = keys[i], b = keys[ixj];
                        bool up = ((i & k) == 0);
                        if ((a > b) == up) { keys[i] = b; keys[ixj] = a; }
                    }
                }
            }
        }
        __syncthreads();
        #pragma unroll
        for (int m = 0; m < 4; m++) {
            int i = m * 256 + t;
            g_perm[i] = (int)(keys[i] & 1023u);
        }
    }
}

// ---------- L1: fused q = pf@Wq+bq, t = q@WkT, beta = q.bk (4 points/CTA, 256 CTAs) ----------
__global__ void __launch_bounds__(256)
k_qt(const float* __restrict__ pf, const float* __restrict__ Wq,
     const float* __restrict__ bq, const float* __restrict__ bk) {
    __shared__ float sp[4][DIM];
    __shared__ float sq[4][DIM];
    int d = threadIdx.x;
    int p0 = blockIdx.x * 4;
    #pragma unroll
    for (int k = 0; k < 4; k++) sp[k][d] = pf[(p0 + k) * DIM + d];
    __syncthreads();

    {   // q phase
        float b = bq[d];
        float acc[4] = {b, b, b, b};
        for (int e = 0; e < DIM; e += 8) {
            float a[8];
            #pragma unroll
            for (int i = 0; i < 8; i++) a[i] = Wq[(e + i) * DIM + d];
            #pragma unroll
            for (int k = 0; k < 4; k++) {
                float4 v1 = *reinterpret_cast<const float4*>(&sp[k][e]);
                float4 v2 = *reinterpret_cast<const float4*>(&sp[k][e + 4]);
                acc[k] += v1.x*a[0] + v1.y*a[1] + v1.z*a[2] + v1.w*a[3]
                        + v2.x*a[4] + v2.y*a[5] + v2.z*a[6] + v2.w*a[7];
            }
        }
        #pragma unroll
        for (int k = 0; k < 4; k++) sq[k][d] = acc[k];
    }
    __syncthreads();

    int wid = d >> 5, lane = d & 31;
    if (wid < 4) {   // beta for p0+wid
        const float4* r4 = reinterpret_cast<const float4*>(&sq[wid][0]);
        const float4* v4 = reinterpret_cast<const float4*>(bk);
        float4 ra = r4[lane], rb = r4[lane + 32];
        float4 va = v4[lane], vb = v4[lane + 32];
        float dp = ra.x*va.x + ra.y*va.y + ra.z*va.z + ra.w*va.w +
                   rb.x*vb.x + rb.y*vb.y + rb.z*vb.z + rb.w*vb.w;
        #pragma unroll
        for (int o = 16; o > 0; o >>= 1) dp += __shfl_xor_sync(0xffffffffu, dp, o);
        if (lane == 0) g_beta[p0 + wid] = dp;
    }

    {   // t phase
        float acc[4] = {0.f, 0.f, 0.f, 0.f};
        for (int j = 0; j < DIM; j += 8) {
            float a[8];
            #pragma unroll
            for (int i = 0; i < 8; i++) a[i] = g_WkT[(j + i) * DIM + d];
            #pragma unroll
            for (int k = 0; k < 4; k++) {
                float4 v1 = *reinterpret_cast<const float4*>(&sq[k][j]);
                float4 v2 = *reinterpret_cast<const float4*>(&sq[k][j + 4]);
                acc[k] += v1.x*a[0] + v1.y*a[1] + v1.z*a[2] + v1.w*a[3]
                        + v2.x*a[4] + v2.y*a[5] + v2.z*a[6] + v2.w*a[7];
            }
        }
        #pragma unroll
        for (int k = 0; k < 4; k++) g_t[(p0 + k) * DIM + d] = acc[k];
    }
}

// ---------- L2: trivial launch (keeps k_attn at launch index 3 for ncu) ----------
__global__ void k_rst() { if (threadIdx.x == 0) g_ctr = 0; }

// ---------- L3: sparse masked attention — Round-4 champion, non-persistent ----------
__global__ void __launch_bounds__(256, 4)
k_attn(const float* __restrict__ bf, const float* __restrict__ boxes) {
    __shared__ float s_xs[SPLIT];
    __shared__ float s_ys[SPLIT];
    __shared__ float s_ws[SPLIT];
    __shared__ unsigned short s_id[SPLIT];
    __shared__ unsigned short s_qq[8][32];
    __shared__ float s_t[GSIZE][DIM];
    __shared__ float4 s_bx[GSIZE];
    __shared__ float s_gbb[4];
    __shared__ int s_wcnt[8], s_woff[8];
    __shared__ int s_run;

    int g = blockIdx.x, s = blockIdx.y;
    int tid = threadIdx.x, wid = tid >> 5, lane = tid & 31;
    int h = lane >> 4, i = lane & 15;
    int p = g_perm[g * GSIZE + wid];

    if (tid < GSIZE) {
        int pp = g_perm[g * GSIZE + tid];
        s_bx[tid] = reinterpret_cast<const float4*>(boxes)[pp];
    }
    {   // stage this warp's t into smem
        const float4* t4 = reinterpret_cast<const float4*>(g_t + (size_t)p * DIM);
        float4 v0 = t4[lane], v1 = t4[lane + 32];
        reinterpret_cast<float4*>(s_t[wid])[lane] = v0;
        reinterpret_cast<float4*>(s_t[wid])[lane + 32] = v1;
    }
    if (tid == 0) s_run = 0;
    __syncthreads();
    if (tid == 0) {
        float gx1 = 1e30f, gy1 = 1e30f, gx2 = -1e30f, gy2 = -1e30f;
        #pragma unroll
        for (int k = 0; k < GSIZE; k++) {
            float4 b = s_bx[k];
            gx1 = fminf(gx1, b.x); gy1 = fminf(gy1, b.y);
            gx2 = fmaxf(gx2, b.z); gy2 = fmaxf(gy2, b.w);
        }
        s_gbb[0] = gx1; s_gbb[1] = gy1; s_gbb[2] = gx2; s_gbb[3] = gy2;
    }
    __syncthreads();
    float gx1 = s_gbb[0], gy1 = s_gbb[1], gx2 = s_gbb[2], gy2 = s_gbb[3];

    // ---- prefilter: deterministic ordered compaction into shortlist ----
    const int base = s * SPLIT;
    #pragma unroll 1
    for (int it = 0; it < SPLIT / 256; it++) {
        int c = base + it * 256 + tid;
        float2 xy = g_cxy[c];
        bool hg = (xy.x > gx1) && (xy.y > gy1) && (xy.x < gx2) && (xy.y < gy2);
        unsigned bal = __ballot_sync(0xffffffffu, hg);
        if (lane == 0) s_wcnt[wid] = __popc(bal);
        __syncthreads();
        if (tid == 0) {
            int r = s_run;
            #pragma unroll
            for (int w = 0; w < 8; w++) { s_woff[w] = r; r += s_wcnt[w]; }
            s_run = r;
        }
        __syncthreads();
        if (hg) {
            int off = s_woff[wid] + __popc(bal & ((1u << lane) - 1u));
            s_xs[off] = xy.x; s_ys[off] = xy.y;
            s_ws[off] = g_wc[c];
            s_id[off] = (unsigned short)c;
        }
    }
    __syncthreads();
    int cnt = s_run;

    // ---- hit loop: half-warp per hit, t from smem ----
    float4 box = s_bx[wid];
    float x1 = box.x, y1 = box.y, x2 = box.z, y2 = box.w;
    float beta = g_beta[p];
    const float4* tv = reinterpret_cast<const float4*>(s_t[wid]);

    float4 a0 = make_float4(0.f,0.f,0.f,0.f), a1 = a0, a2 = a0, a3 = a0;
    float ssum = 0.f;

    for (int sl = 0; sl < cnt; sl += 32) {
        __syncwarp();
        int idx = sl + lane;
        bool valid = idx < cnt;
        float cx = s_xs[idx];   // oob-by-<32 reads land in s_ys: gated by valid
        float cy = s_ys[idx];
        bool hit = valid && (cx > x1) && (cy > y1) && (cx < x2) && (cy < y2);
        unsigned bal = __ballot_sync(0xffffffffu, hit);
        int nh = __popc(bal);
        if (hit) s_qq[wid][__popc(bal & ((1u << lane) - 1u))] = (unsigned short)idx;
        __syncwarp();
        for (int j = 0; j < nh; j += 2) {
            int qi = j + h;                 // half h processes hit j+h
            bool v = qi < nh;
            int pos = s_qq[wid][v ? qi : 0];
            int ch = s_id[pos];
            float wc = s_ws[pos];
            const float4* r = reinterpret_cast<const float4*>(bf + (size_t)ch * DIM);
            float4 r0 = r[i], r1 = r[i + 16], r2 = r[i + 32], r3 = r[i + 48];
            float4 t0 = tv[i], t1 = tv[i + 16], t2 = tv[i + 32], t3 = tv[i + 48];
            float dp = r0.x*t0.x + r0.y*t0.y + r0.z*t0.z + r0.w*t0.w
                     + r1.x*t1.x + r1.y*t1.y + r1.z*t1.z + r1.w*t1.w
                     + r2.x*t2.x + r2.y*t2.y + r2.z*t2.z + r2.w*t2.w
                     + r3.x*t3.x + r3.y*t3.y + r3.z*t3.z + r3.w*t3.w;
            dp += __shfl_xor_sync(0xffffffffu, dp, 8);
            dp += __shfl_xor_sync(0xffffffffu, dp, 4);
            dp += __shfl_xor_sync(0xffffffffu, dp, 2);
            dp += __shfl_xor_sync(0xffffffffu, dp, 1);
            float logit = fminf(fmaxf(wc * dp + beta, -50.f), 50.f);
            // logits clipped to <=50; fixed reference replaces online max
            float w = __expf(logit - 50.f);
            if (!v) w = 0.f;
            ssum += w;
            a0.x += w*r0.x; a0.y += w*r0.y; a0.z += w*r0.z; a0.w += w*r0.w;
            a1.x += w*r1.x; a1.y += w*r1.y; a1.z += w*r1.z; a1.w += w*r1.w;
            a2.x += w*r2.x; a2.y += w*r2.y; a2.z += w*r2.z; a2.w += w*r2.w;
            a3.x += w*r3.x; a3.y += w*r3.y; a3.z += w*r3.z; a3.w += w*r3.w;
        }
    }

    // cross-half combine
    ssum += __shfl_xor_sync(0xffffffffu, ssum, 16);
    a0.x += __shfl_xor_sync(0xffffffffu, a0.x, 16);
    a0.y += __shfl_xor_sync(0xffffffffu, a0.y, 16);
    a0.z += __shfl_xor_sync(0xffffffffu, a0.z, 16);
    a0.w += __shfl_xor_sync(0xffffffffu, a0.w, 16);
    a1.x += __shfl_xor_sync(0xffffffffu, a1.x, 16);
    a1.y += __shfl_xor_sync(0xffffffffu, a1.y, 16);
    a1.z += __shfl_xor_sync(0xffffffffu, a1.z, 16);
    a1.w += __shfl_xor_sync(0xffffffffu, a1.w, 16);
    a2.x += __shfl_xor_sync(0xffffffffu, a2.x, 16);
    a2.y += __shfl_xor_sync(0xffffffffu, a2.y, 16);
    a2.z += __shfl_xor_sync(0xffffffffu, a2.z, 16);
    a2.w += __shfl_xor_sync(0xffffffffu, a2.w, 16);
    a3.x += __shfl_xor_sync(0xffffffffu, a3.x, 16);
    a3.y += __shfl_xor_sync(0xffffffffu, a3.y, 16);
    a3.z += __shfl_xor_sync(0xffffffffu, a3.z, 16);
    a3.w += __shfl_xor_sync(0xffffffffu, a3.w, 16);

    int slot = p * NSPLIT + s;
    if (h == 0) {
        float4* pa = reinterpret_cast<float4*>(g_pacc + (size_t)slot * DIM);
        pa[i] = a0; pa[i + 16] = a1; pa[i + 32] = a2; pa[i + 48] = a3;
    }
    if (lane == 0) g_ps[slot] = ssum;
}

// ---------- L4: combine partials + residual ----------
__global__ void __launch_bounds__(256) k_combine(const float* __restrict__ pf,
                                                 float* __restrict__ out) {
    int p = blockIdx.x;
    int d = threadIdx.x;
    float num = 0.f, den = 0.f;
    #pragma unroll 8
    for (int s = 0; s < NSPLIT; s++) {
        den += g_ps[p * NSPLIT + s];
        num += g_pacc[(size_t)(p * NSPLIT + s) * DIM + d];
    }
    float merge = (den > 0.f) ? (num / den) : 0.f;
    out[p * DIM + d] = pf[p * DIM + d] + merge;
}

extern "C" void kernel_launch(void* const* d_in, const int* in_sizes, int n_in,
                              void* d_out, int out_size) {
    const float* points_feat = (const float*)d_in[0];
    const float* box_feat    = (const float*)d_in[1];
    const float* centers     = (const float*)d_in[2];
    const float* boxes       = (const float*)d_in[3];
    const float* Wq          = (const float*)d_in[4];
    const float* bq          = (const float*)d_in[5];
    const float* Wk          = (const float*)d_in[6];
    const float* bk          = (const float*)d_in[7];
    const float* scales      = (const float*)d_in[8];
    float* out = (float*)d_out;

    k_pre<<<321, 256>>>(Wk, centers, scales, boxes);   // launch 0
    k_qt<<<NPTS / 4, 256>>>(points_feat, Wq, bq, bk);  // launch 1
    k_rst<<<1, 32>>>();                                // launch 2
    dim3 agrid(NGROUP, NSPLIT);
    k_attn<<<agrid, 256>>>(box_feat, boxes);           // launch 3 (ncu target)
    k_combine<<<NPTS, 256>>>(points_feat, out);        // launch 4
}

// round 14
// speedup vs baseline: 1.1003x; 1.0424x over previous
#include <cuda_runtime.h>
#include <math.h>

#define NCAND 65536
#define NPTS  1024
#define DIM   256
#define NSPLIT 32
#define SPLIT (NCAND / NSPLIT)   // 2048
#define GSIZE 8                  // points per group (warp per point)
#define NGROUP (NPTS / GSIZE)    // 128

// ---- scratch (__device__ globals; no allocation allowed) ----
__device__ float  g_WkT[DIM * DIM];    // WkT[j,d] = Wk[d,j]
__device__ float  g_t[NPTS * DIM];     // t = (pf@Wq+bq) @ WkT
__device__ float  g_beta[NPTS];        // q . bk
__device__ float2 g_cxy[NCAND];        // candidate (xs, ys)
__device__ float  g_wc[NCAND];         // scales[lvl]
__device__ int    g_perm[NPTS];        // morton-sorted point order
__device__ float4 g_gbb[NGROUP];       // per-group union bbox
__device__ float  g_ps[NPTS * NSPLIT];                    // partial weight sums
__device__ float  g_pacc[(size_t)NPTS * NSPLIT * DIM];    // partial accumulators

// ---------- L0: transpose Wk (0..63) + cand prep (64..319) ----------
__global__ void __launch_bounds__(256)
k_pre(const float* __restrict__ Wk,
      const float* __restrict__ centers,
      const float* __restrict__ scales) {
    int bx = blockIdx.x, t = threadIdx.x;
    if (bx < 64) {
        __shared__ float tl[32][33];
        int bi = bx & 7, bj = bx >> 3;
        int tx = t & 31, ty = t >> 5;
        #pragma unroll
        for (int r = 0; r < 4; r++)
            tl[ty + 8 * r][tx] = Wk[(bj * 32 + ty + 8 * r) * DIM + bi * 32 + tx];
        __syncthreads();
        #pragma unroll
        for (int r = 0; r < 4; r++)
            g_WkT[(bi * 32 + ty + 8 * r) * DIM + bj * 32 + tx] = tl[tx][ty + 8 * r];
    } else {
        int c = (bx - 64) * 256 + t;
        float4 ct = reinterpret_cast<const float4*>(centers)[c];
        float s = ct.z;
        float half = s * 0.5f;               // stride is exact power of 2
        g_cxy[c] = make_float2(ct.y + half, ct.x + half);   // (xs, ys)
        int lvl = ((__float_as_int(s) >> 23) & 255) - 127 - 3;
        g_wc[c] = scales[lvl];
    }
}

// ---------- L1: blocks 0..255: q = pf@Wq+bq, t = q@WkT, beta = q.bk (4 pts/CTA)
//              block 256: morton bitonic sort (runs concurrently) ----------
__global__ void __launch_bounds__(256)
k_qt(const float* __restrict__ pf, const float* __restrict__ Wq,
     const float* __restrict__ bq, const float* __restrict__ bk,
     const float* __restrict__ boxes) {
    int d = threadIdx.x;
    if (blockIdx.x == 256) {
        // morton bitonic sort (256 threads, 4 items each), stable via idx-in-key
        __shared__ unsigned keys[NPTS];
        #pragma unroll
        for (int m = 0; m < 4; m++) {
            int i = m * 256 + d;
            float cx = 0.5f * (boxes[i * 4 + 0] + boxes[i * 4 + 2]);
            float cy = 0.5f * (boxes[i * 4 + 1] + boxes[i * 4 + 3]);
            unsigned kx = min(255u, (unsigned)(fmaxf(cx, 0.f) * 0.25f));
            unsigned ky = min(255u, (unsigned)(fmaxf(cy, 0.f) * 0.25f));
            unsigned mo = 0;
            #pragma unroll
            for (int b = 0; b < 8; b++)
                mo |= (((kx >> b) & 1u) << (2 * b)) | (((ky >> b) & 1u) << (2 * b + 1));
            keys[i] = (mo << 10) | (unsigned)i;
        }
        for (unsigned k = 2; k <= NPTS; k <<= 1) {
            for (unsigned j = k >> 1; j > 0; j >>= 1) {
                __syncthreads();
                #pragma unroll
                for (int m = 0; m < 4; m++) {
                    unsigned i = m * 256 + d;
                    unsigned ixj = i ^ j;
                    if (ixj > i) {
                        unsigned a = keys[i], b = keys[ixj];
                        bool up = ((i & k) == 0);
                        if ((a > b) == up) { keys[i] = b; keys[ixj] = a; }
                    }
                }
            }
        }
        __syncthreads();
        #pragma unroll
        for (int m = 0; m < 4; m++) {
            int i = m * 256 + d;
            g_perm[i] = (int)(keys[i] & 1023u);
        }
        return;
    }

    __shared__ float sp[4][DIM];
    __shared__ float sq[4][DIM];
    int p0 = blockIdx.x * 4;
    #pragma unroll
    for (int k = 0; k < 4; k++) sp[k][d] = pf[(p0 + k) * DIM + d];
    __syncthreads();

    {   // q phase
        float b = bq[d];
        float acc[4] = {b, b, b, b};
        for (int e = 0; e < DIM; e += 8) {
            float a[8];
            #pragma unroll
            for (int i = 0; i < 8; i++) a[i] = Wq[(e + i) * DIM + d];
            #pragma unroll
            for (int k = 0; k < 4; k++) {
                float4 v1 = *reinterpret_cast<const float4*>(&sp[k][e]);
                float4 v2 = *reinterpret_cast<const float4*>(&sp[k][e + 4]);
                acc[k] += v1.x*a[0] + v1.y*a[1] + v1.z*a[2] + v1.w*a[3]
                        + v2.x*a[4] + v2.y*a[5] + v2.z*a[6] + v2.w*a[7];
            }
        }
        #pragma unroll
        for (int k = 0; k < 4; k++) sq[k][d] = acc[k];
    }
    __syncthreads();

    int wid = d >> 5, lane = d & 31;
    if (wid < 4) {   // beta for p0+wid
        const float4* r4 = reinterpret_cast<const float4*>(&sq[wid][0]);
        const float4* v4 = reinterpret_cast<const float4*>(bk);
        float4 ra = r4[lane], rb = r4[lane + 32];
        float4 va = v4[lane], vb = v4[lane + 32];
        float dp = ra.x*va.x + ra.y*va.y + ra.z*va.z + ra.w*va.w +
                   rb.x*vb.x + rb.y*vb.y + rb.z*vb.z + rb.w*vb.w;
        #pragma unroll
        for (int o = 16; o > 0; o >>= 1) dp += __shfl_xor_sync(0xffffffffu, dp, o);
        if (lane == 0) g_beta[p0 + wid] = dp;
    }

    {   // t phase
        float acc[4] = {0.f, 0.f, 0.f, 0.f};
        for (int j = 0; j < DIM; j += 8) {
            float a[8];
            #pragma unroll
            for (int i = 0; i < 8; i++) a[i] = g_WkT[(j + i) * DIM + d];
            #pragma unroll
            for (int k = 0; k < 4; k++) {
                float4 v1 = *reinterpret_cast<const float4*>(&sq[k][j]);
                float4 v2 = *reinterpret_cast<const float4*>(&sq[k][j + 4]);
                acc[k] += v1.x*a[0] + v1.y*a[1] + v1.z*a[2] + v1.w*a[3]
                        + v2.x*a[4] + v2.y*a[5] + v2.z*a[6] + v2.w*a[7];
            }
        }
        #pragma unroll
        for (int k = 0; k < 4; k++) g_t[(p0 + k) * DIM + d] = acc[k];
    }
}

// ---------- L2: group bboxes (also keeps k_attn at launch index 3 for ncu) ----------
__global__ void __launch_bounds__(128)
k_gbb(const float* __restrict__ boxes) {
    int g = threadIdx.x;   // 128 groups
    float gx1 = 1e30f, gy1 = 1e30f, gx2 = -1e30f, gy2 = -1e30f;
    #pragma unroll
    for (int k = 0; k < GSIZE; k++) {
        int p = g_perm[g * GSIZE + k];
        float4 b = reinterpret_cast<const float4*>(boxes)[p];
        gx1 = fminf(gx1, b.x); gy1 = fminf(gy1, b.y);
        gx2 = fmaxf(gx2, b.z); gy2 = fmaxf(gy2, b.w);
    }
    g_gbb[g] = make_float4(gx1, gy1, gx2, gy2);
}

// ---------- L3: sparse masked attention — stable champion, non-persistent ----------
__global__ void __launch_bounds__(256, 4)
k_attn(const float* __restrict__ bf, const float* __restrict__ boxes) {
    __shared__ float s_xs[SPLIT];
    __shared__ float s_ys[SPLIT];
    __shared__ float s_ws[SPLIT];
    __shared__ unsigned short s_id[SPLIT];
    __shared__ unsigned short s_qq[8][32];
    __shared__ float s_t[GSIZE][DIM];
    __shared__ float4 s_bx[GSIZE];
    __shared__ int s_wcnt[8], s_woff[8];
    __shared__ int s_run;

    int g = blockIdx.x, s = blockIdx.y;
    int tid = threadIdx.x, wid = tid >> 5, lane = tid & 31;
    int h = lane >> 4, i = lane & 15;
    int p = g_perm[g * GSIZE + wid];

    if (tid < GSIZE) {
        int pp = g_perm[g * GSIZE + tid];
        s_bx[tid] = reinterpret_cast<const float4*>(boxes)[pp];
    }
    {   // stage this warp's t into smem
        const float4* t4 = reinterpret_cast<const float4*>(g_t + (size_t)p * DIM);
        float4 v0 = t4[lane], v1 = t4[lane + 32];
        reinterpret_cast<float4*>(s_t[wid])[lane] = v0;
        reinterpret_cast<float4*>(s_t[wid])[lane + 32] = v1;
    }
    if (tid == 0) s_run = 0;
    float4 gb = g_gbb[g];        // precomputed group bbox (broadcast load)
    float gx1 = gb.x, gy1 = gb.y, gx2 = gb.z, gy2 = gb.w;
    __syncthreads();

    // ---- prefilter: deterministic ordered compaction into shortlist ----
    const int base = s * SPLIT;
    #pragma unroll 1
    for (int it = 0; it < SPLIT / 256; it++) {
        int c = base + it * 256 + tid;
        float2 xy = g_cxy[c];
        bool hg = (xy.x > gx1) && (xy.y > gy1) && (xy.x < gx2) && (xy.y < gy2);
        unsigned bal = __ballot_sync(0xffffffffu, hg);
        if (lane == 0) s_wcnt[wid] = __popc(bal);
        __syncthreads();
        if (tid == 0) {
            int r = s_run;
            #pragma unroll
            for (int w = 0; w < 8; w++) { s_woff[w] = r; r += s_wcnt[w]; }
            s_run = r;
        }
        __syncthreads();
        if (hg) {
            int off = s_woff[wid] + __popc(bal & ((1u << lane) - 1u));
            s_xs[off] = xy.x; s_ys[off] = xy.y;
            s_ws[off] = g_wc[c];
            s_id[off] = (unsigned short)c;
        }
    }
    __syncthreads();
    int cnt = s_run;

    // ---- hit loop: half-warp per hit, t from smem ----
    float4 box = s_bx[wid];
    float x1 = box.x, y1 = box.y, x2 = box.z, y2 = box.w;
    float beta = g_beta[p];
    const float4* tv = reinterpret_cast<const float4*>(s_t[wid]);

    float4 a0 = make_float4(0.f,0.f,0.f,0.f), a1 = a0, a2 = a0, a3 = a0;
    float ssum = 0.f;

    for (int sl = 0; sl < cnt; sl += 32) {
        __syncwarp();
        int idx = sl + lane;
        bool valid = idx < cnt;
        float cx = s_xs[idx];   // oob-by-<32 reads land in s_ys: gated by valid
        float cy = s_ys[idx];
        bool hit = valid && (cx > x1) && (cy > y1) && (cx < x2) && (cy < y2);
        unsigned bal = __ballot_sync(0xffffffffu, hit);
        int nh = __popc(bal);
        if (hit) s_qq[wid][__popc(bal & ((1u << lane) - 1u))] = (unsigned short)idx;
        __syncwarp();
        for (int j = 0; j < nh; j += 2) {
            int qi = j + h;                 // half h processes hit j+h
            bool v = qi < nh;
            int pos = s_qq[wid][v ? qi : 0];
            int ch = s_id[pos];
            float wc = s_ws[pos];
            const float4* r = reinterpret_cast<const float4*>(bf + (size_t)ch * DIM);
            float4 r0 = r[i], r1 = r[i + 16], r2 = r[i + 32], r3 = r[i + 48];
            float4 t0 = tv[i], t1 = tv[i + 16], t2 = tv[i + 32], t3 = tv[i + 48];
            float dp = r0.x*t0.x + r0.y*t0.y + r0.z*t0.z + r0.w*t0.w
                     + r1.x*t1.x + r1.y*t1.y + r1.z*t1.z + r1.w*t1.w
                     + r2.x*t2.x + r2.y*t2.y + r2.z*t2.z + r2.w*t2.w
                     + r3.x*t3.x + r3.y*t3.y + r3.z*t3.z + r3.w*t3.w;
            dp += __shfl_xor_sync(0xffffffffu, dp, 8);
            dp += __shfl_xor_sync(0xffffffffu, dp, 4);
            dp += __shfl_xor_sync(0xffffffffu, dp, 2);
            dp += __shfl_xor_sync(0xffffffffu, dp, 1);
            float logit = fminf(fmaxf(wc * dp + beta, -50.f), 50.f);
            // logits clipped to <=50; fixed reference replaces online max
            float w = __expf(logit - 50.f);
            if (!v) w = 0.f;
            ssum += w;
            a0.x += w*r0.x; a0.y += w*r0.y; a0.z += w*r0.z; a0.w += w*r0.w;
            a1.x += w*r1.x; a1.y += w*r1.y; a1.z += w*r1.z; a1.w += w*r1.w;
            a2.x += w*r2.x; a2.y += w*r2.y; a2.z += w*r2.z; a2.w += w*r2.w;
            a3.x += w*r3.x; a3.y += w*r3.y; a3.z += w*r3.z; a3.w += w*r3.w;
        }
    }

    // cross-half combine
    ssum += __shfl_xor_sync(0xffffffffu, ssum, 16);
    a0.x += __shfl_xor_sync(0xffffffffu, a0.x, 16);
    a0.y += __shfl_xor_sync(0xffffffffu, a0.y, 16);
    a0.z += __shfl_xor_sync(0xffffffffu, a0.z, 16);
    a0.w += __shfl_xor_sync(0xffffffffu, a0.w, 16);
    a1.x += __shfl_xor_sync(0xffffffffu, a1.x, 16);
    a1.y += __shfl_xor_sync(0xffffffffu, a1.y, 16);
    a1.z += __shfl_xor_sync(0xffffffffu, a1.z, 16);
    a1.w += __shfl_xor_sync(0xffffffffu, a1.w, 16);
    a2.x += __shfl_xor_sync(0xffffffffu, a2.x, 16);
    a2.y += __shfl_xor_sync(0xffffffffu, a2.y, 16);
    a2.z += __shfl_xor_sync(0xffffffffu, a2.z, 16);
    a2.w += __shfl_xor_sync(0xffffffffu, a2.w, 16);
    a3.x += __shfl_xor_sync(0xffffffffu, a3.x, 16);
    a3.y += __shfl_xor_sync(0xffffffffu, a3.y, 16);
    a3.z += __shfl_xor_sync(0xffffffffu, a3.z, 16);
    a3.w += __shfl_xor_sync(0xffffffffu, a3.w, 16);

    int slot = p * NSPLIT + s;
    if (h == 0) {
        float4* pa = reinterpret_cast<float4*>(g_pacc + (size_t)slot * DIM);
        pa[i] = a0; pa[i + 16] = a1; pa[i + 32] = a2; pa[i + 48] = a3;
    }
    if (lane == 0) g_ps[slot] = ssum;
}

// ---------- L4: combine partials + residual (float4, 64 threads/point) ----------
__global__ void __launch_bounds__(64) k_combine(const float* __restrict__ pf,
                                                float* __restrict__ out) {
    int p = blockIdx.x;
    int t = threadIdx.x;   // 64 threads, each owns 4 dims
    float4 num = make_float4(0.f, 0.f, 0.f, 0.f);
    float den = 0.f;
    const float4* pa = reinterpret_cast<const float4*>(g_pacc + (size_t)p * NSPLIT * DIM);
    #pragma unroll 8
    for (int s = 0; s < NSPLIT; s++) {
        den += g_ps[p * NSPLIT + s];
        float4 v = pa[s * 64 + t];
        num.x += v.x; num.y += v.y; num.z += v.z; num.w += v.w;
    }
    float inv = (den > 0.f) ? (1.f / den) : 0.f;
    float4 base = reinterpret_cast<const float4*>(pf)[p * 64 + t];
    reinterpret_cast<float4*>(out)[p * 64 + t] =
        make_float4(base.x + num.x * inv, base.y + num.y * inv,
                    base.z + num.z * inv, base.w + num.w * inv);
}

extern "C" void kernel_launch(void* const* d_in, const int* in_sizes, int n_in,
                              void* d_out, int out_size) {
    const float* points_feat = (const float*)d_in[0];
    const float* box_feat    = (const float*)d_in[1];
    const float* centers     = (const float*)d_in[2];
    const float* boxes       = (const float*)d_in[3];
    const float* Wq          = (const float*)d_in[4];
    const float* bq          = (const float*)d_in[5];
    const float* Wk          = (const float*)d_in[6];
    const float* bk          = (const float*)d_in[7];
    const float* scales      = (const float*)d_in[8];
    float* out = (float*)d_out;

    k_pre<<<320, 256>>>(Wk, centers, scales);                    // launch 0
    k_qt<<<257, 256>>>(points_feat, Wq, bq, bk, boxes);          // launch 1
    k_gbb<<<1, 128>>>(boxes);                                    // launch 2
    dim3 agrid(NGROUP, NSPLIT);
    k_attn<<<agrid, 256>>>(box_feat, boxes);                     // launch 3 (ncu target)
    k_combine<<<NPTS, 64>>>(points_feat, out);                   // launch 4
}

// round 15
// speedup vs baseline: 1.1230x; 1.0206x over previous
#include <cuda_runtime.h>
#include <math.h>

#define NCAND 65536
#define NPTS  1024
#define DIM   256
#define NSPLIT 32
#define SPLIT (NCAND / NSPLIT)   // 2048
#define GSIZE 8                  // points per group (warp per point)
#define NGROUP (NPTS / GSIZE)    // 128

// ---- scratch (__device__ globals; no allocation allowed) ----
__device__ float  g_WkT[DIM * DIM];    // WkT[j,d] = Wk[d,j]
__device__ float  g_t[NPTS * DIM];     // t = (pf@Wq+bq) @ WkT
__device__ float  g_beta[NPTS];        // q . bk
__device__ float2 g_cxy[NCAND];        // candidate (xs, ys)
__device__ float  g_wc[NCAND];         // scales[lvl]
__device__ int    g_perm[NPTS];        // morton-sorted point order
__device__ float4 g_gbb[NGROUP];       // per-group union bbox
__device__ float  g_ps[NPTS * NSPLIT];                    // partial weight sums
__device__ float  g_pacc[(size_t)NPTS * NSPLIT * DIM];    // partial accumulators

// ---------- L0: transpose Wk (0..63) + cand prep (64..319) ----------
__global__ void __launch_bounds__(256)
k_pre(const float* __restrict__ Wk,
      const float* __restrict__ centers,
      const float* __restrict__ scales) {
    int bx = blockIdx.x, t = threadIdx.x;
    if (bx < 64) {
        __shared__ float tl[32][33];
        int bi = bx & 7, bj = bx >> 3;
        int tx = t & 31, ty = t >> 5;
        #pragma unroll
        for (int r = 0; r < 4; r++)
            tl[ty + 8 * r][tx] = Wk[(bj * 32 + ty + 8 * r) * DIM + bi * 32 + tx];
        __syncthreads();
        #pragma unroll
        for (int r = 0; r < 4; r++)
            g_WkT[(bi * 32 + ty + 8 * r) * DIM + bj * 32 + tx] = tl[tx][ty + 8 * r];
    } else {
        int c = (bx - 64) * 256 + t;
        float4 ct = reinterpret_cast<const float4*>(centers)[c];
        float s = ct.z;
        float half = s * 0.5f;               // stride is exact power of 2
        g_cxy[c] = make_float2(ct.y + half, ct.x + half);   // (xs, ys)
        int lvl = ((__float_as_int(s) >> 23) & 255) - 127 - 3;
        g_wc[c] = scales[lvl];
    }
}

// ---------- L1: blocks 0..511: q = pf@Wq+bq, t = q@WkT, beta = q.bk (2 pts/CTA)
//              block 512: morton bitonic sort (runs concurrently) ----------
__global__ void __launch_bounds__(256)
k_qt(const float* __restrict__ pf, const float* __restrict__ Wq,
     const float* __restrict__ bq, const float* __restrict__ bk,
     const float* __restrict__ boxes) {
    int d = threadIdx.x;
    if (blockIdx.x == 512) {
        // morton bitonic sort (256 threads, 4 items each), stable via idx-in-key
        __shared__ unsigned keys[NPTS];
        #pragma unroll
        for (int m = 0; m < 4; m++) {
            int i = m * 256 + d;
            float cx = 0.5f * (boxes[i * 4 + 0] + boxes[i * 4 + 2]);
            float cy = 0.5f * (boxes[i * 4 + 1] + boxes[i * 4 + 3]);
            unsigned kx = min(255u, (unsigned)(fmaxf(cx, 0.f) * 0.25f));
            unsigned ky = min(255u, (unsigned)(fmaxf(cy, 0.f) * 0.25f));
            unsigned mo = 0;
            #pragma unroll
            for (int b = 0; b < 8; b++)
                mo |= (((kx >> b) & 1u) << (2 * b)) | (((ky >> b) & 1u) << (2 * b + 1));
            keys[i] = (mo << 10) | (unsigned)i;
        }
        for (unsigned k = 2; k <= NPTS; k <<= 1) {
            for (unsigned j = k >> 1; j > 0; j >>= 1) {
                __syncthreads();
                #pragma unroll
                for (int m = 0; m < 4; m++) {
                    unsigned i = m * 256 + d;
                    unsigned ixj = i ^ j;
                    if (ixj > i) {
                        unsigned a = keys[i], b = keys[ixj];
                        bool up = ((i & k) == 0);
                        if ((a > b) == up) { keys[i] = b; keys[ixj] = a; }
                    }
                }
            }
        }
        __syncthreads();
        #pragma unroll
        for (int m = 0; m < 4; m++) {
            int i = m * 256 + d;
            g_perm[i] = (int)(keys[i] & 1023u);
        }
        return;
    }

    __shared__ float sp[2][DIM];
    __shared__ float sq[2][DIM];
    int p0 = blockIdx.x * 2;
    sp[0][d] = pf[p0 * DIM + d];
    sp[1][d] = pf[(p0 + 1) * DIM + d];
    __syncthreads();

    {   // q phase
        float b = bq[d];
        float acc0 = b, acc1 = b;
        for (int e = 0; e < DIM; e += 8) {
            float a[8];
            #pragma unroll
            for (int i = 0; i < 8; i++) a[i] = Wq[(e + i) * DIM + d];
            #pragma unroll
            for (int k = 0; k < 2; k++) {
                float4 v1 = *reinterpret_cast<const float4*>(&sp[k][e]);
                float4 v2 = *reinterpret_cast<const float4*>(&sp[k][e + 4]);
                float sacc = v1.x*a[0] + v1.y*a[1] + v1.z*a[2] + v1.w*a[3]
                           + v2.x*a[4] + v2.y*a[5] + v2.z*a[6] + v2.w*a[7];
                if (k == 0) acc0 += sacc; else acc1 += sacc;
            }
        }
        sq[0][d] = acc0;
        sq[1][d] = acc1;
    }
    __syncthreads();

    int wid = d >> 5, lane = d & 31;
    if (wid < 2) {   // beta for p0+wid
        const float4* r4 = reinterpret_cast<const float4*>(&sq[wid][0]);
        const float4* v4 = reinterpret_cast<const float4*>(bk);
        float4 ra = r4[lane], rb = r4[lane + 32];
        float4 va = v4[lane], vb = v4[lane + 32];
        float dp = ra.x*va.x + ra.y*va.y + ra.z*va.z + ra.w*va.w +
                   rb.x*vb.x + rb.y*vb.y + rb.z*vb.z + rb.w*vb.w;
        #pragma unroll
        for (int o = 16; o > 0; o >>= 1) dp += __shfl_xor_sync(0xffffffffu, dp, o);
        if (lane == 0) g_beta[p0 + wid] = dp;
    }

    {   // t phase
        float acc0 = 0.f, acc1 = 0.f;
        for (int j = 0; j < DIM; j += 8) {
            float a[8];
            #pragma unroll
            for (int i = 0; i < 8; i++) a[i] = g_WkT[(j + i) * DIM + d];
            #pragma unroll
            for (int k = 0; k < 2; k++) {
                float4 v1 = *reinterpret_cast<const float4*>(&sq[k][j]);
                float4 v2 = *reinterpret_cast<const float4*>(&sq[k][j + 4]);
                float sacc = v1.x*a[0] + v1.y*a[1] + v1.z*a[2] + v1.w*a[3]
                           + v2.x*a[4] + v2.y*a[5] + v2.z*a[6] + v2.w*a[7];
                if (k == 0) acc0 += sacc; else acc1 += sacc;
            }
        }
        g_t[p0 * DIM + d] = acc0;
        g_t[(p0 + 1) * DIM + d] = acc1;
    }
}

// ---------- L2: group bboxes (also keeps k_attn at launch index 3 for ncu) ----------
__global__ void __launch_bounds__(128)
k_gbb(const float* __restrict__ boxes) {
    int g = threadIdx.x;   // 128 groups
    float gx1 = 1e30f, gy1 = 1e30f, gx2 = -1e30f, gy2 = -1e30f;
    #pragma unroll
    for (int k = 0; k < GSIZE; k++) {
        int p = g_perm[g * GSIZE + k];
        float4 b = reinterpret_cast<const float4*>(boxes)[p];
        gx1 = fminf(gx1, b.x); gy1 = fminf(gy1, b.y);
        gx2 = fmaxf(gx2, b.z); gy2 = fmaxf(gy2, b.w);
    }
    g_gbb[g] = make_float4(gx1, gy1, gx2, gy2);
}

// ---------- L3: sparse masked attention — stable champion, non-persistent ----------
__global__ void __launch_bounds__(256, 4)
k_attn(const float* __restrict__ bf, const float* __restrict__ boxes) {
    __shared__ float s_xs[SPLIT];
    __shared__ float s_ys[SPLIT];
    __shared__ float s_ws[SPLIT];
    __shared__ unsigned short s_id[SPLIT];
    __shared__ unsigned short s_qq[8][32];
    __shared__ float s_t[GSIZE][DIM];
    __shared__ float4 s_bx[GSIZE];
    __shared__ int s_wcnt[8], s_woff[8];
    __shared__ int s_run;

    int g = blockIdx.x, s = blockIdx.y;
    int tid = threadIdx.x, wid = tid >> 5, lane = tid & 31;
    int h = lane >> 4, i = lane & 15;
    int p = g_perm[g * GSIZE + wid];

    if (tid < GSIZE) {
        int pp = g_perm[g * GSIZE + tid];
        s_bx[tid] = reinterpret_cast<const float4*>(boxes)[pp];
    }
    {   // stage this warp's t into smem
        const float4* t4 = reinterpret_cast<const float4*>(g_t + (size_t)p * DIM);
        float4 v0 = t4[lane], v1 = t4[lane + 32];
        reinterpret_cast<float4*>(s_t[wid])[lane] = v0;
        reinterpret_cast<float4*>(s_t[wid])[lane + 32] = v1;
    }
    if (tid == 0) s_run = 0;
    float4 gb = g_gbb[g];        // precomputed group bbox (broadcast load)
    float gx1 = gb.x, gy1 = gb.y, gx2 = gb.z, gy2 = gb.w;
    __syncthreads();

    // ---- prefilter: deterministic ordered compaction into shortlist ----
    const int base = s * SPLIT;
    #pragma unroll 1
    for (int it = 0; it < SPLIT / 256; it++) {
        int c = base + it * 256 + tid;
        float2 xy = g_cxy[c];
        bool hg = (xy.x > gx1) && (xy.y > gy1) && (xy.x < gx2) && (xy.y < gy2);
        unsigned bal = __ballot_sync(0xffffffffu, hg);
        if (lane == 0) s_wcnt[wid] = __popc(bal);
        __syncthreads();
        if (tid == 0) {
            int r = s_run;
            #pragma unroll
            for (int w = 0; w < 8; w++) { s_woff[w] = r; r += s_wcnt[w]; }
            s_run = r;
        }
        __syncthreads();
        if (hg) {
            int off = s_woff[wid] + __popc(bal & ((1u << lane) - 1u));
            s_xs[off] = xy.x; s_ys[off] = xy.y;
            s_ws[off] = g_wc[c];
            s_id[off] = (unsigned short)c;
        }
    }
    __syncthreads();
    int cnt = s_run;

    // ---- hit loop: half-warp per hit, t from smem ----
    float4 box = s_bx[wid];
    float x1 = box.x, y1 = box.y, x2 = box.z, y2 = box.w;
    float beta = g_beta[p];
    const float4* tv = reinterpret_cast<const float4*>(s_t[wid]);

    float4 a0 = make_float4(0.f,0.f,0.f,0.f), a1 = a0, a2 = a0, a3 = a0;
    float ssum = 0.f;

    for (int sl = 0; sl < cnt; sl += 32) {
        __syncwarp();
        int idx = sl + lane;
        bool valid = idx < cnt;
        float cx = s_xs[idx];   // oob-by-<32 reads land in s_ys: gated by valid
        float cy = s_ys[idx];
        bool hit = valid && (cx > x1) && (cy > y1) && (cx < x2) && (cy < y2);
        unsigned bal = __ballot_sync(0xffffffffu, hit);
        int nh = __popc(bal);
        if (hit) s_qq[wid][__popc(bal & ((1u << lane) - 1u))] = (unsigned short)idx;
        __syncwarp();
        for (int j = 0; j < nh; j += 2) {
            int qi = j + h;                 // half h processes hit j+h
            bool v = qi < nh;
            int pos = s_qq[wid][v ? qi : 0];
            int ch = s_id[pos];
            float wc = s_ws[pos];
            const float4* r = reinterpret_cast<const float4*>(bf + (size_t)ch * DIM);
            float4 r0 = r[i], r1 = r[i + 16], r2 = r[i + 32], r3 = r[i + 48];
            float4 t0 = tv[i], t1 = tv[i + 16], t2 = tv[i + 32], t3 = tv[i + 48];
            float dp = r0.x*t0.x + r0.y*t0.y + r0.z*t0.z + r0.w*t0.w
                     + r1.x*t1.x + r1.y*t1.y + r1.z*t1.z + r1.w*t1.w
                     + r2.x*t2.x + r2.y*t2.y + r2.z*t2.z + r2.w*t2.w
                     + r3.x*t3.x + r3.y*t3.y + r3.z*t3.z + r3.w*t3.w;
            dp += __shfl_xor_sync(0xffffffffu, dp, 8);
            dp += __shfl_xor_sync(0xffffffffu, dp, 4);
            dp += __shfl_xor_sync(0xffffffffu, dp, 2);
            dp += __shfl_xor_sync(0xffffffffu, dp, 1);
            float logit = fminf(fmaxf(wc * dp + beta, -50.f), 50.f);
            // logits clipped to <=50; fixed reference replaces online max
            float w = __expf(logit - 50.f);
            if (!v) w = 0.f;
            ssum += w;
            a0.x += w*r0.x; a0.y += w*r0.y; a0.z += w*r0.z; a0.w += w*r0.w;
            a1.x += w*r1.x; a1.y += w*r1.y; a1.z += w*r1.z; a1.w += w*r1.w;
            a2.x += w*r2.x; a2.y += w*r2.y; a2.z += w*r2.z; a2.w += w*r2.w;
            a3.x += w*r3.x; a3.y += w*r3.y; a3.z += w*r3.z; a3.w += w*r3.w;
        }
    }

    // cross-half combine
    ssum += __shfl_xor_sync(0xffffffffu, ssum, 16);
    a0.x += __shfl_xor_sync(0xffffffffu, a0.x, 16);
    a0.y += __shfl_xor_sync(0xffffffffu, a0.y, 16);
    a0.z += __shfl_xor_sync(0xffffffffu, a0.z, 16);
    a0.w += __shfl_xor_sync(0xffffffffu, a0.w, 16);
    a1.x += __shfl_xor_sync(0xffffffffu, a1.x, 16);
    a1.y += __shfl_xor_sync(0xffffffffu, a1.y, 16);
    a1.z += __shfl_xor_sync(0xffffffffu, a1.z, 16);
    a1.w += __shfl_xor_sync(0xffffffffu, a1.w, 16);
    a2.x += __shfl_xor_sync(0xffffffffu, a2.x, 16);
    a2.y += __shfl_xor_sync(0xffffffffu, a2.y, 16);
    a2.z += __shfl_xor_sync(0xffffffffu, a2.z, 16);
    a2.w += __shfl_xor_sync(0xffffffffu, a2.w, 16);
    a3.x += __shfl_xor_sync(0xffffffffu, a3.x, 16);
    a3.y += __shfl_xor_sync(0xffffffffu, a3.y, 16);
    a3.z += __shfl_xor_sync(0xffffffffu, a3.z, 16);
    a3.w += __shfl_xor_sync(0xffffffffu, a3.w, 16);

    int slot = p * NSPLIT + s;
    if (h == 0) {
        float4* pa = reinterpret_cast<float4*>(g_pacc + (size_t)slot * DIM);
        pa[i] = a0; pa[i + 16] = a1; pa[i + 32] = a2; pa[i + 48] = a3;
    }
    if (lane == 0) g_ps[slot] = ssum;
}

// ---------- L4: combine partials + residual (float4, 64 threads/point) ----------
__global__ void __launch_bounds__(64) k_combine(const float* __restrict__ pf,
                                                float* __restrict__ out) {
    int p = blockIdx.x;
    int t = threadIdx.x;   // 64 threads, each owns 4 dims
    float4 num = make_float4(0.f, 0.f, 0.f, 0.f);
    float den = 0.f;
    const float4* pa = reinterpret_cast<const float4*>(g_pacc + (size_t)p * NSPLIT * DIM);
    #pragma unroll 8
    for (int s = 0; s < NSPLIT; s++) {
        den += g_ps[p * NSPLIT + s];
        float4 v = pa[s * 64 + t];
        num.x += v.x; num.y += v.y; num.z += v.z; num.w += v.w;
    }
    float inv = (den > 0.f) ? (1.f / den) : 0.f;
    float4 base = reinterpret_cast<const float4*>(pf)[p * 64 + t];
    reinterpret_cast<float4*>(out)[p * 64 + t] =
        make_float4(base.x + num.x * inv, base.y + num.y * inv,
                    base.z + num.z * inv, base.w + num.w * inv);
}

extern "C" void kernel_launch(void* const* d_in, const int* in_sizes, int n_in,
                              void* d_out, int out_size) {
    const float* points_feat = (const float*)d_in[0];
    const float* box_feat    = (const float*)d_in[1];
    const float* centers     = (const float*)d_in[2];
    const float* boxes       = (const float*)d_in[3];
    const float* Wq          = (const float*)d_in[4];
    const float* bq          = (const float*)d_in[5];
    const float* Wk          = (const float*)d_in[6];
    const float* bk          = (const float*)d_in[7];
    const float* scales      = (const float*)d_in[8];
    float* out = (float*)d_out;

    k_pre<<<320, 256>>>(Wk, centers, scales);                    // launch 0
    k_qt<<<513, 256>>>(points_feat, Wq, bq, bk, boxes);          // launch 1
    k_gbb<<<1, 128>>>(boxes);                                    // launch 2
    dim3 agrid(NGROUP, NSPLIT);
    k_attn<<<agrid, 256>>>(box_feat, boxes);                     // launch 3 (ncu target)
    k_combine<<<NPTS, 64>>>(points_feat, out);                   // launch 4
}

// round 16
// speedup vs baseline: 1.1413x; 1.0163x over previous
#include <cuda_runtime.h>
#include <math.h>

#define NCAND 65536
#define NPTS  1024
#define DIM   256
#define NSPLIT 32
#define SPLIT (NCAND / NSPLIT)   // 2048
#define GSIZE 8                  // points per group (warp per point)
#define NGROUP (NPTS / GSIZE)    // 128

// ---- scratch (__device__ globals; no allocation allowed) ----
__device__ float  g_WkT[DIM * DIM];    // WkT[j,d] = Wk[d,j]
__device__ float  g_t[NPTS * DIM];     // t = (pf@Wq+bq) @ WkT
__device__ float  g_beta[NPTS];        // q . bk
__device__ float2 g_cxy[NCAND];        // candidate (xs, ys)
__device__ float  g_wc[NCAND];         // scales[lvl]
__device__ int    g_perm[NPTS];        // morton-sorted point order
__device__ float4 g_gbb[NGROUP];       // per-group union bbox
__device__ int    g_nop;               // dummy target
__device__ float  g_ps[NPTS * NSPLIT];                    // partial weight sums
__device__ float  g_pacc[(size_t)NPTS * NSPLIT * DIM];    // partial accumulators

// ---------- L0: transpose Wk (0..63) + cand prep (64..319) ----------
__global__ void __launch_bounds__(256)
k_pre(const float* __restrict__ Wk,
      const float* __restrict__ centers,
      const float* __restrict__ scales) {
    int bx = blockIdx.x, t = threadIdx.x;
    if (bx < 64) {
        __shared__ float tl[32][33];
        int bi = bx & 7, bj = bx >> 3;
        int tx = t & 31, ty = t >> 5;
        #pragma unroll
        for (int r = 0; r < 4; r++)
            tl[ty + 8 * r][tx] = Wk[(bj * 32 + ty + 8 * r) * DIM + bi * 32 + tx];
        __syncthreads();
        #pragma unroll
        for (int r = 0; r < 4; r++)
            g_WkT[(bi * 32 + ty + 8 * r) * DIM + bj * 32 + tx] = tl[tx][ty + 8 * r];
    } else {
        int c = (bx - 64) * 256 + t;
        float4 ct = reinterpret_cast<const float4*>(centers)[c];
        float s = ct.z;
        float half = s * 0.5f;               // stride is exact power of 2
        g_cxy[c] = make_float2(ct.y + half, ct.x + half);   // (xs, ys)
        int lvl = ((__float_as_int(s) >> 23) & 255) - 127 - 3;
        g_wc[c] = scales[lvl];
    }
}

// ---------- L1: blocks 0..511: q = pf@Wq+bq, t = q@WkT, beta = q.bk (2 pts/CTA)
//              block 512: morton bitonic sort + group bboxes (concurrent) ----------
__global__ void __launch_bounds__(256)
k_qt(const float* __restrict__ pf, const float* __restrict__ Wq,
     const float* __restrict__ bq, const float* __restrict__ bk,
     const float* __restrict__ boxes) {
    int d = threadIdx.x;
    if (blockIdx.x == 512) {
        // morton bitonic sort (256 threads, 4 items each), stable via idx-in-key
        __shared__ unsigned keys[NPTS];
        #pragma unroll
        for (int m = 0; m < 4; m++) {
            int i = m * 256 + d;
            float cx = 0.5f * (boxes[i * 4 + 0] + boxes[i * 4 + 2]);
            float cy = 0.5f * (boxes[i * 4 + 1] + boxes[i * 4 + 3]);
            unsigned kx = min(255u, (unsigned)(fmaxf(cx, 0.f) * 0.25f));
            unsigned ky = min(255u, (unsigned)(fmaxf(cy, 0.f) * 0.25f));
            unsigned mo = 0;
            #pragma unroll
            for (int b = 0; b < 8; b++)
                mo |= (((kx >> b) & 1u) << (2 * b)) | (((ky >> b) & 1u) << (2 * b + 1));
            keys[i] = (mo << 10) | (unsigned)i;
        }
        for (unsigned k = 2; k <= NPTS; k <<= 1) {
            for (unsigned j = k >> 1; j > 0; j >>= 1) {
                __syncthreads();
                #pragma unroll
                for (int m = 0; m < 4; m++) {
                    unsigned i = m * 256 + d;
                    unsigned ixj = i ^ j;
                    if (ixj > i) {
                        unsigned a = keys[i], b = keys[ixj];
                        bool up = ((i & k) == 0);
                        if ((a > b) == up) { keys[i] = b; keys[ixj] = a; }
                    }
                }
            }
        }
        __syncthreads();
        #pragma unroll
        for (int m = 0; m < 4; m++) {
            int i = m * 256 + d;
            g_perm[i] = (int)(keys[i] & 1023u);
        }
        __syncthreads();
        if (d < NGROUP) {   // group bboxes from sorted keys (in smem)
            float gx1 = 1e30f, gy1 = 1e30f, gx2 = -1e30f, gy2 = -1e30f;
            #pragma unroll
            for (int k = 0; k < GSIZE; k++) {
                int p = (int)(keys[d * GSIZE + k] & 1023u);
                float4 b = reinterpret_cast<const float4*>(boxes)[p];
                gx1 = fminf(gx1, b.x); gy1 = fminf(gy1, b.y);
                gx2 = fmaxf(gx2, b.z); gy2 = fmaxf(gy2, b.w);
            }
            g_gbb[d] = make_float4(gx1, gy1, gx2, gy2);
        }
        return;
    }

    __shared__ float sp[2][DIM];
    __shared__ float sq[2][DIM];
    int p0 = blockIdx.x * 2;
    sp[0][d] = pf[p0 * DIM + d];
    sp[1][d] = pf[(p0 + 1) * DIM + d];
    __syncthreads();

    {   // q phase
        float b = bq[d];
        float acc0 = b, acc1 = b;
        for (int e = 0; e < DIM; e += 8) {
            float a[8];
            #pragma unroll
            for (int i = 0; i < 8; i++) a[i] = Wq[(e + i) * DIM + d];
            #pragma unroll
            for (int k = 0; k < 2; k++) {
                float4 v1 = *reinterpret_cast<const float4*>(&sp[k][e]);
                float4 v2 = *reinterpret_cast<const float4*>(&sp[k][e + 4]);
                float sacc = v1.x*a[0] + v1.y*a[1] + v1.z*a[2] + v1.w*a[3]
                           + v2.x*a[4] + v2.y*a[5] + v2.z*a[6] + v2.w*a[7];
                if (k == 0) acc0 += sacc; else acc1 += sacc;
            }
        }
        sq[0][d] = acc0;
        sq[1][d] = acc1;
    }
    __syncthreads();

    int wid = d >> 5, lane = d & 31;
    if (wid < 2) {   // beta for p0+wid
        const float4* r4 = reinterpret_cast<const float4*>(&sq[wid][0]);
        const float4* v4 = reinterpret_cast<const float4*>(bk);
        float4 ra = r4[lane], rb = r4[lane + 32];
        float4 va = v4[lane], vb = v4[lane + 32];
        float dp = ra.x*va.x + ra.y*va.y + ra.z*va.z + ra.w*va.w +
                   rb.x*vb.x + rb.y*vb.y + rb.z*vb.z + rb.w*vb.w;
        #pragma unroll
        for (int o = 16; o > 0; o >>= 1) dp += __shfl_xor_sync(0xffffffffu, dp, o);
        if (lane == 0) g_beta[p0 + wid] = dp;
    }

    {   // t phase
        float acc0 = 0.f, acc1 = 0.f;
        for (int j = 0; j < DIM; j += 8) {
            float a[8];
            #pragma unroll
            for (int i = 0; i < 8; i++) a[i] = g_WkT[(j + i) * DIM + d];
            #pragma unroll
            for (int k = 0; k < 2; k++) {
                float4 v1 = *reinterpret_cast<const float4*>(&sq[k][j]);
                float4 v2 = *reinterpret_cast<const float4*>(&sq[k][j + 4]);
                float sacc = v1.x*a[0] + v1.y*a[1] + v1.z*a[2] + v1.w*a[3]
                           + v2.x*a[4] + v2.y*a[5] + v2.z*a[6] + v2.w*a[7];
                if (k == 0) acc0 += sacc; else acc1 += sacc;
            }
        }
        g_t[p0 * DIM + d] = acc0;
        g_t[(p0 + 1) * DIM + d] = acc1;
    }
}

// ---------- L2: no-op (keeps k_attn at launch index 3 for ncu) ----------
__global__ void k_nop() { if (threadIdx.x == 1024) g_nop = 1; }

// ---------- L3: sparse masked attention — champion + direct-id queue ----------
__global__ void __launch_bounds__(256, 4)
k_attn(const float* __restrict__ bf, const float* __restrict__ boxes) {
    __shared__ float s_xs[SPLIT];
    __shared__ float s_ys[SPLIT];
    __shared__ float s_ws[SPLIT];
    __shared__ unsigned short s_id[SPLIT];
    __shared__ unsigned short s_qq[8][32];   // candidate id (direct)
    __shared__ float s_qw[8][32];            // wc (direct)
    __shared__ float s_t[GSIZE][DIM];
    __shared__ float4 s_bx[GSIZE];
    __shared__ int s_wcnt[8], s_woff[8];
    __shared__ int s_run;

    int g = blockIdx.x, s = blockIdx.y;
    int tid = threadIdx.x, wid = tid >> 5, lane = tid & 31;
    int h = lane >> 4, i = lane & 15;
    int p = g_perm[g * GSIZE + wid];

    if (tid < GSIZE) {
        int pp = g_perm[g * GSIZE + tid];
        s_bx[tid] = reinterpret_cast<const float4*>(boxes)[pp];
    }
    {   // stage this warp's t into smem
        const float4* t4 = reinterpret_cast<const float4*>(g_t + (size_t)p * DIM);
        float4 v0 = t4[lane], v1 = t4[lane + 32];
        reinterpret_cast<float4*>(s_t[wid])[lane] = v0;
        reinterpret_cast<float4*>(s_t[wid])[lane + 32] = v1;
    }
    if (tid == 0) s_run = 0;
    float4 gb = g_gbb[g];        // precomputed group bbox (broadcast load)
    float gx1 = gb.x, gy1 = gb.y, gx2 = gb.z, gy2 = gb.w;
    __syncthreads();

    // ---- prefilter: deterministic ordered compaction into shortlist ----
    const int base = s * SPLIT;
    #pragma unroll 1
    for (int it = 0; it < SPLIT / 256; it++) {
        int c = base + it * 256 + tid;
        float2 xy = g_cxy[c];
        bool hg = (xy.x > gx1) && (xy.y > gy1) && (xy.x < gx2) && (xy.y < gy2);
        unsigned bal = __ballot_sync(0xffffffffu, hg);
        if (lane == 0) s_wcnt[wid] = __popc(bal);
        __syncthreads();
        if (tid == 0) {
            int r = s_run;
            #pragma unroll
            for (int w = 0; w < 8; w++) { s_woff[w] = r; r += s_wcnt[w]; }
            s_run = r;
        }
        __syncthreads();
        if (hg) {
            int off = s_woff[wid] + __popc(bal & ((1u << lane) - 1u));
            s_xs[off] = xy.x; s_ys[off] = xy.y;
            s_ws[off] = g_wc[c];
            s_id[off] = (unsigned short)c;
        }
    }
    __syncthreads();
    int cnt = s_run;

    // ---- hit loop: half-warp per hit, t from smem, direct-id queue ----
    float4 box = s_bx[wid];
    float x1 = box.x, y1 = box.y, x2 = box.z, y2 = box.w;
    float beta = g_beta[p];
    const float4* tv = reinterpret_cast<const float4*>(s_t[wid]);

    float4 a0 = make_float4(0.f,0.f,0.f,0.f), a1 = a0, a2 = a0, a3 = a0;
    float ssum = 0.f;

    for (int sl = 0; sl < cnt; sl += 32) {
        __syncwarp();
        int idx = sl + lane;
        bool valid = idx < cnt;
        float cx = s_xs[idx];   // oob-by-<32 reads land in s_ys: gated by valid
        float cy = s_ys[idx];
        bool hit = valid && (cx > x1) && (cy > y1) && (cx < x2) && (cy < y2);
        unsigned bal = __ballot_sync(0xffffffffu, hit);
        int nh = __popc(bal);
        if (hit) {
            int cpos = __popc(bal & ((1u << lane) - 1u));
            s_qq[wid][cpos] = s_id[idx];   // candidate id fetched in parallel
            s_qw[wid][cpos] = s_ws[idx];   // wc fetched in parallel
        }
        __syncwarp();
        for (int j = 0; j < nh; j += 2) {
            int qi = j + h;                 // half h processes hit j+h
            bool v = qi < nh;
            int sel = v ? qi : 0;
            int ch = s_qq[wid][sel];
            float wc = s_qw[wid][sel];
            const float4* r = reinterpret_cast<const float4*>(bf + (size_t)ch * DIM);
            float4 r0 = r[i], r1 = r[i + 16], r2 = r[i + 32], r3 = r[i + 48];
            float4 t0 = tv[i], t1 = tv[i + 16], t2 = tv[i + 32], t3 = tv[i + 48];
            float dp = r0.x*t0.x + r0.y*t0.y + r0.z*t0.z + r0.w*t0.w
                     + r1.x*t1.x + r1.y*t1.y + r1.z*t1.z + r1.w*t1.w
                     + r2.x*t2.x + r2.y*t2.y + r2.z*t2.z + r2.w*t2.w
                     + r3.x*t3.x + r3.y*t3.y + r3.z*t3.z + r3.w*t3.w;
            dp += __shfl_xor_sync(0xffffffffu, dp, 8);
            dp += __shfl_xor_sync(0xffffffffu, dp, 4);
            dp += __shfl_xor_sync(0xffffffffu, dp, 2);
            dp += __shfl_xor_sync(0xffffffffu, dp, 1);
            float logit = fminf(fmaxf(wc * dp + beta, -50.f), 50.f);
            // logits clipped to <=50; fixed reference replaces online max
            float w = __expf(logit - 50.f);
            if (!v) w = 0.f;
            ssum += w;
            a0.x += w*r0.x; a0.y += w*r0.y; a0.z += w*r0.z; a0.w += w*r0.w;
            a1.x += w*r1.x; a1.y += w*r1.y; a1.z += w*r1.z; a1.w += w*r1.w;
            a2.x += w*r2.x; a2.y += w*r2.y; a2.z += w*r2.z; a2.w += w*r2.w;
            a3.x += w*r3.x; a3.y += w*r3.y; a3.z += w*r3.z; a3.w += w*r3.w;
        }
    }

    // cross-half combine
    ssum += __shfl_xor_sync(0xffffffffu, ssum, 16);
    a0.x += __shfl_xor_sync(0xffffffffu, a0.x, 16);
    a0.y += __shfl_xor_sync(0xffffffffu, a0.y, 16);
    a0.z += __shfl_xor_sync(0xffffffffu, a0.z, 16);
    a0.w += __shfl_xor_sync(0xffffffffu, a0.w, 16);
    a1.x += __shfl_xor_sync(0xffffffffu, a1.x, 16);
    a1.y += __shfl_xor_sync(0xffffffffu, a1.y, 16);
    a1.z += __shfl_xor_sync(0xffffffffu, a1.z, 16);
    a1.w += __shfl_xor_sync(0xffffffffu, a1.w, 16);
    a2.x += __shfl_xor_sync(0xffffffffu, a2.x, 16);
    a2.y += __shfl_xor_sync(0xffffffffu, a2.y, 16);
    a2.z += __shfl_xor_sync(0xffffffffu, a2.z, 16);
    a2.w += __shfl_xor_sync(0xffffffffu, a2.w, 16);
    a3.x += __shfl_xor_sync(0xffffffffu, a3.x, 16);
    a3.y += __shfl_xor_sync(0xffffffffu, a3.y, 16);
    a3.z += __shfl_xor_sync(0xffffffffu, a3.z, 16);
    a3.w += __shfl_xor_sync(0xffffffffu, a3.w, 16);

    int slot = p * NSPLIT + s;
    if (h == 0) {
        float4* pa = reinterpret_cast<float4*>(g_pacc + (size_t)slot * DIM);
        pa[i] = a0; pa[i + 16] = a1; pa[i + 32] = a2; pa[i + 48] = a3;
    }
    if (lane == 0) g_ps[slot] = ssum;
}

// ---------- L4: combine partials + residual (float4, 64 threads/point) ----------
__global__ void __launch_bounds__(64) k_combine(const float* __restrict__ pf,
                                                float* __restrict__ out) {
    int p = blockIdx.x;
    int t = threadIdx.x;   // 64 threads, each owns 4 dims
    float4 num = make_float4(0.f, 0.f, 0.f, 0.f);
    float den = 0.f;
    const float4* pa = reinterpret_cast<const float4*>(g_pacc + (size_t)p * NSPLIT * DIM);
    #pragma unroll 8
    for (int s = 0; s < NSPLIT; s++) {
        den += g_ps[p * NSPLIT + s];
        float4 v = pa[s * 64 + t];
        num.x += v.x; num.y += v.y; num.z += v.z; num.w += v.w;
    }
    float inv = (den > 0.f) ? (1.f / den) : 0.f;
    float4 base = reinterpret_cast<const float4*>(pf)[p * 64 + t];
    reinterpret_cast<float4*>(out)[p * 64 + t] =
        make_float4(base.x + num.x * inv, base.y + num.y * inv,
                    base.z + num.z * inv, base.w + num.w * inv);
}

extern "C" void kernel_launch(void* const* d_in, const int* in_sizes, int n_in,
                              void* d_out, int out_size) {
    const float* points_feat = (const float*)d_in[0];
    const float* box_feat    = (const float*)d_in[1];
    const float* centers     = (const float*)d_in[2];
    const float* boxes       = (const float*)d_in[3];
    const float* Wq          = (const float*)d_in[4];
    const float* bq          = (const float*)d_in[5];
    const float* Wk          = (const float*)d_in[6];
    const float* bk          = (const float*)d_in[7];
    const float* scales      = (const float*)d_in[8];
    float* out = (float*)d_out;

    k_pre<<<320, 256>>>(Wk, centers, scales);                    // launch 0
    k_qt<<<513, 256>>>(points_feat, Wq, bq, bk, boxes);          // launch 1
    k_nop<<<1, 32>>>();                                          // launch 2
    dim3 agrid(NGROUP, NSPLIT);
    k_attn<<<agrid, 256>>>(box_feat, boxes);                     // launch 3 (ncu target)
    k_combine<<<NPTS, 64>>>(points_feat, out);                   // launch 4
}

// round 17
// speedup vs baseline: 1.1710x; 1.0260x over previous
#include <cuda_runtime.h>
#include <math.h>

#define NCAND 65536
#define NPTS  1024
#define DIM   256
#define NSPLIT 32
#define SPLIT (NCAND / NSPLIT)   // 2048
#define GSIZE 8                  // points per group (warp per point)
#define NGROUP (NPTS / GSIZE)    // 128

// ---- scratch (__device__ globals; no allocation allowed) ----
__device__ float  g_WkT[DIM * DIM];    // WkT[j,d] = Wk[d,j]
__device__ float  g_q[NPTS * DIM];     // q = pf @ Wq + bq
__device__ float  g_t[NPTS * DIM];     // t = q @ WkT
__device__ float  g_beta[NPTS];        // q . bk
__device__ float2 g_cxy[NCAND];        // candidate (xs, ys)
__device__ float  g_wc[NCAND];         // scales[lvl]
__device__ int    g_perm[NPTS];        // morton-sorted point order
__device__ float4 g_gbb[NGROUP];       // per-group union bbox
__device__ float  g_ps[NPTS * NSPLIT];                    // partial weight sums
__device__ float  g_pacc[(size_t)NPTS * NSPLIT * DIM];    // partial accumulators

// ---------- L0: transpose (0..63) | cand prep (64..319) | sort+gbb (320)
//              | q = pf@Wq+bq and beta = q.bk (321..832, 2 pts/CTA) ----------
__global__ void __launch_bounds__(256)
k_misc(const float* __restrict__ Wk,
       const float* __restrict__ centers,
       const float* __restrict__ scales,
       const float* __restrict__ boxes,
       const float* __restrict__ pf,
       const float* __restrict__ Wq,
       const float* __restrict__ bq,
       const float* __restrict__ bk) {
    int bx = blockIdx.x, t = threadIdx.x;
    if (bx < 64) {
        __shared__ float tl[32][33];
        int bi = bx & 7, bj = bx >> 3;
        int tx = t & 31, ty = t >> 5;
        #pragma unroll
        for (int r = 0; r < 4; r++)
            tl[ty + 8 * r][tx] = Wk[(bj * 32 + ty + 8 * r) * DIM + bi * 32 + tx];
        __syncthreads();
        #pragma unroll
        for (int r = 0; r < 4; r++)
            g_WkT[(bi * 32 + ty + 8 * r) * DIM + bj * 32 + tx] = tl[tx][ty + 8 * r];
    } else if (bx < 320) {
        int c = (bx - 64) * 256 + t;
        float4 ct = reinterpret_cast<const float4*>(centers)[c];
        float s = ct.z;
        float half = s * 0.5f;               // stride is exact power of 2
        g_cxy[c] = make_float2(ct.y + half, ct.x + half);   // (xs, ys)
        int lvl = ((__float_as_int(s) >> 23) & 255) - 127 - 3;
        g_wc[c] = scales[lvl];
    } else if (bx == 320) {
        // morton bitonic sort (256 threads, 4 items each), stable via idx-in-key
        __shared__ unsigned keys[NPTS];
        #pragma unroll
        for (int m = 0; m < 4; m++) {
            int i = m * 256 + t;
            float cx = 0.5f * (boxes[i * 4 + 0] + boxes[i * 4 + 2]);
            float cy = 0.5f * (boxes[i * 4 + 1] + boxes[i * 4 + 3]);
            unsigned kx = min(255u, (unsigned)(fmaxf(cx, 0.f) * 0.25f));
            unsigned ky = min(255u, (unsigned)(fmaxf(cy, 0.f) * 0.25f));
            unsigned mo = 0;
            #pragma unroll
            for (int b = 0; b < 8; b++)
                mo |= (((kx >> b) & 1u) << (2 * b)) | (((ky >> b) & 1u) << (2 * b + 1));
            keys[i] = (mo << 10) | (unsigned)i;
        }
        for (unsigned k = 2; k <= NPTS; k <<= 1) {
            for (unsigned j = k >> 1; j > 0; j >>= 1) {
                __syncthreads();
                #pragma unroll
                for (int m = 0; m < 4; m++) {
                    unsigned i = m * 256 + t;
                    unsigned ixj = i ^ j;
                    if (ixj > i) {
                        unsigned a = keys[i], b = keys[ixj];
                        bool up = ((i & k) == 0);
                        if ((a > b) == up) { keys[i] = b; keys[ixj] = a; }
                    }
                }
            }
        }
        __syncthreads();
        #pragma unroll
        for (int m = 0; m < 4; m++) {
            int i = m * 256 + t;
            g_perm[i] = (int)(keys[i] & 1023u);
        }
        __syncthreads();
        if (t < NGROUP) {   // group bboxes from sorted keys (in smem)
            float gx1 = 1e30f, gy1 = 1e30f, gx2 = -1e30f, gy2 = -1e30f;
            #pragma unroll
            for (int k = 0; k < GSIZE; k++) {
                int p = (int)(keys[t * GSIZE + k] & 1023u);
                float4 b = reinterpret_cast<const float4*>(boxes)[p];
                gx1 = fminf(gx1, b.x); gy1 = fminf(gy1, b.y);
                gx2 = fmaxf(gx2, b.z); gy2 = fmaxf(gy2, b.w);
            }
            g_gbb[t] = make_float4(gx1, gy1, gx2, gy2);
        }
    } else {
        // q + beta for 2 points
        __shared__ float sp[2][DIM];
        __shared__ float sq[2][DIM];
        int d = t;
        int p0 = (bx - 321) * 2;
        sp[0][d] = pf[p0 * DIM + d];
        sp[1][d] = pf[(p0 + 1) * DIM + d];
        __syncthreads();

        float b = bq[d];
        float acc0 = b, acc1 = b;
        for (int e = 0; e < DIM; e += 8) {
            float a[8];
            #pragma unroll
            for (int i = 0; i < 8; i++) a[i] = Wq[(e + i) * DIM + d];
            #pragma unroll
            for (int k = 0; k < 2; k++) {
                float4 v1 = *reinterpret_cast<const float4*>(&sp[k][e]);
                float4 v2 = *reinterpret_cast<const float4*>(&sp[k][e + 4]);
                float sacc = v1.x*a[0] + v1.y*a[1] + v1.z*a[2] + v1.w*a[3]
                           + v2.x*a[4] + v2.y*a[5] + v2.z*a[6] + v2.w*a[7];
                if (k == 0) acc0 += sacc; else acc1 += sacc;
            }
        }
        g_q[p0 * DIM + d] = acc0;
        g_q[(p0 + 1) * DIM + d] = acc1;
        sq[0][d] = acc0;
        sq[1][d] = acc1;
        __syncthreads();

        int wid = d >> 5, lane = d & 31;
        if (wid < 2) {   // beta for p0+wid
            const float4* r4 = reinterpret_cast<const float4*>(&sq[wid][0]);
            const float4* v4 = reinterpret_cast<const float4*>(bk);
            float4 ra = r4[lane], rb = r4[lane + 32];
            float4 va = v4[lane], vb = v4[lane + 32];
            float dp = ra.x*va.x + ra.y*va.y + ra.z*va.z + ra.w*va.w +
                       rb.x*vb.x + rb.y*vb.y + rb.z*vb.z + rb.w*vb.w;
            #pragma unroll
            for (int o = 16; o > 0; o >>= 1) dp += __shfl_xor_sync(0xffffffffu, dp, o);
            if (lane == 0) g_beta[p0 + wid] = dp;
        }
    }
}

// ---------- L1: t = q @ WkT (2 points per CTA, 512 CTAs) ----------
__global__ void __launch_bounds__(256)
k_t(int unused) {
    __shared__ float sq[2][DIM];
    int d = threadIdx.x;
    int p0 = blockIdx.x * 2;
    sq[0][d] = g_q[p0 * DIM + d];
    sq[1][d] = g_q[(p0 + 1) * DIM + d];
    __syncthreads();

    float acc0 = 0.f, acc1 = 0.f;
    for (int j = 0; j < DIM; j += 8) {
        float a[8];
        #pragma unroll
        for (int i = 0; i < 8; i++) a[i] = g_WkT[(j + i) * DIM + d];
        #pragma unroll
        for (int k = 0; k < 2; k++) {
            float4 v1 = *reinterpret_cast<const float4*>(&sq[k][j]);
            float4 v2 = *reinterpret_cast<const float4*>(&sq[k][j + 4]);
            float sacc = v1.x*a[0] + v1.y*a[1] + v1.z*a[2] + v1.w*a[3]
                       + v2.x*a[4] + v2.y*a[5] + v2.z*a[6] + v2.w*a[7];
            if (k == 0) acc0 += sacc; else acc1 += sacc;
        }
    }
    g_t[p0 * DIM + d] = acc0;
    g_t[(p0 + 1) * DIM + d] = acc1;
}

// ---------- L2: sparse masked attention — champion + one-sync prefilter ----------
__global__ void __launch_bounds__(256, 4)
k_attn(const float* __restrict__ bf, const float* __restrict__ boxes) {
    __shared__ float s_xs[SPLIT];
    __shared__ float s_ys[SPLIT];
    __shared__ float s_ws[SPLIT];
    __shared__ unsigned short s_id[SPLIT];
    __shared__ unsigned short s_qq[8][32];   // candidate id (direct)
    __shared__ float s_qw[8][32];            // wc (direct)
    __shared__ float s_t[GSIZE][DIM];
    __shared__ float4 s_bx[GSIZE];
    __shared__ int s_wcnt[2][8];             // double-buffered warp counts

    int g = blockIdx.x, s = blockIdx.y;
    int tid = threadIdx.x, wid = tid >> 5, lane = tid & 31;
    int h = lane >> 4, i = lane & 15;
    int p = g_perm[g * GSIZE + wid];

    if (tid < GSIZE) {
        int pp = g_perm[g * GSIZE + tid];
        s_bx[tid] = reinterpret_cast<const float4*>(boxes)[pp];
    }
    {   // stage this warp's t into smem (read by same warp only)
        const float4* t4 = reinterpret_cast<const float4*>(g_t + (size_t)p * DIM);
        float4 v0 = t4[lane], v1 = t4[lane + 32];
        reinterpret_cast<float4*>(s_t[wid])[lane] = v0;
        reinterpret_cast<float4*>(s_t[wid])[lane + 32] = v1;
    }
    float4 gb = g_gbb[g];        // precomputed group bbox (broadcast load)
    float gx1 = gb.x, gy1 = gb.y, gx2 = gb.z, gy2 = gb.w;

    // ---- prefilter: ordered compaction, ONE sync per iteration ----
    const int base = s * SPLIT;
    int run = 0;
    #pragma unroll 1
    for (int it = 0; it < SPLIT / 256; it++) {
        int c = base + it * 256 + tid;
        float2 xy = g_cxy[c];
        bool hg = (xy.x > gx1) && (xy.y > gy1) && (xy.x < gx2) && (xy.y < gy2);
        unsigned bal = __ballot_sync(0xffffffffu, hg);
        if (lane == 0) s_wcnt[it & 1][wid] = __popc(bal);
        __syncthreads();
        int pre = 0, tot = 0;
        #pragma unroll
        for (int w = 0; w < 8; w++) {
            int v = s_wcnt[it & 1][w];
            if (w < wid) pre += v;
            tot += v;
        }
        if (hg) {
            int off = run + pre + __popc(bal & ((1u << lane) - 1u));
            s_xs[off] = xy.x; s_ys[off] = xy.y;
            s_ws[off] = g_wc[c];
            s_id[off] = (unsigned short)c;
        }
        run += tot;
    }
    int cnt = run;               // every thread holds the total
    __syncthreads();             // shortlist + s_bx + s_t visible

    // ---- hit loop: half-warp per hit, t from smem, direct-id queue ----
    float4 box = s_bx[wid];
    float x1 = box.x, y1 = box.y, x2 = box.z, y2 = box.w;
    float beta = g_beta[p];
    const float4* tv = reinterpret_cast<const float4*>(s_t[wid]);

    float4 a0 = make_float4(0.f,0.f,0.f,0.f), a1 = a0, a2 = a0, a3 = a0;
    float ssum = 0.f;

    for (int sl = 0; sl < cnt; sl += 32) {
        __syncwarp();
        int idx = sl + lane;
        bool valid = idx < cnt;
        float cx = s_xs[idx];   // oob-by-<32 reads land in s_ys: gated by valid
        float cy = s_ys[idx];
        bool hit = valid && (cx > x1) && (cy > y1) && (cx < x2) && (cy < y2);
        unsigned bal = __ballot_sync(0xffffffffu, hit);
        int nh = __popc(bal);
        if (hit) {
            int cpos = __popc(bal & ((1u << lane) - 1u));
            s_qq[wid][cpos] = s_id[idx];   // candidate id fetched in parallel
            s_qw[wid][cpos] = s_ws[idx];   // wc fetched in parallel
        }
        __syncwarp();
        for (int j = 0; j < nh; j += 2) {
            int qi = j + h;                 // half h processes hit j+h
            bool v = qi < nh;
            int sel = v ? qi : 0;
            int ch = s_qq[wid][sel];
            float wc = s_qw[wid][sel];
            const float4* r = reinterpret_cast<const float4*>(bf + (size_t)ch * DIM);
            float4 r0 = r[i], r1 = r[i + 16], r2 = r[i + 32], r3 = r[i + 48];
            float4 t0 = tv[i], t1 = tv[i + 16], t2 = tv[i + 32], t3 = tv[i + 48];
            float dp = r0.x*t0.x + r0.y*t0.y + r0.z*t0.z + r0.w*t0.w
                     + r1.x*t1.x + r1.y*t1.y + r1.z*t1.z + r1.w*t1.w
                     + r2.x*t2.x + r2.y*t2.y + r2.z*t2.z + r2.w*t2.w
                     + r3.x*t3.x + r3.y*t3.y + r3.z*t3.z + r3.w*t3.w;
            dp += __shfl_xor_sync(0xffffffffu, dp, 8);
            dp += __shfl_xor_sync(0xffffffffu, dp, 4);
            dp += __shfl_xor_sync(0xffffffffu, dp, 2);
            dp += __shfl_xor_sync(0xffffffffu, dp, 1);
            float logit = fminf(fmaxf(wc * dp + beta, -50.f), 50.f);
            // logits clipped to <=50; fixed reference replaces online max
            float w = __expf(logit - 50.f);
            if (!v) w = 0.f;
            ssum += w;
            a0.x += w*r0.x; a0.y += w*r0.y; a0.z += w*r0.z; a0.w += w*r0.w;
            a1.x += w*r1.x; a1.y += w*r1.y; a1.z += w*r1.z; a1.w += w*r1.w;
            a2.x += w*r2.x; a2.y += w*r2.y; a2.z += w*r2.z; a2.w += w*r2.w;
            a3.x += w*r3.x; a3.y += w*r3.y; a3.z += w*r3.z; a3.w += w*r3.w;
        }
    }

    // cross-half combine
    ssum += __shfl_xor_sync(0xffffffffu, ssum, 16);
    a0.x += __shfl_xor_sync(0xffffffffu, a0.x, 16);
    a0.y += __shfl_xor_sync(0xffffffffu, a0.y, 16);
    a0.z += __shfl_xor_sync(0xffffffffu, a0.z, 16);
    a0.w += __shfl_xor_sync(0xffffffffu, a0.w, 16);
    a1.x += __shfl_xor_sync(0xffffffffu, a1.x, 16);
    a1.y += __shfl_xor_sync(0xffffffffu, a1.y, 16);
    a1.z += __shfl_xor_sync(0xffffffffu, a1.z, 16);
    a1.w += __shfl_xor_sync(0xffffffffu, a1.w, 16);
    a2.x += __shfl_xor_sync(0xffffffffu, a2.x, 16);
    a2.y += __shfl_xor_sync(0xffffffffu, a2.y, 16);
    a2.z += __shfl_xor_sync(0xffffffffu, a2.z, 16);
    a2.w += __shfl_xor_sync(0xffffffffu, a2.w, 16);
    a3.x += __shfl_xor_sync(0xffffffffu, a3.x, 16);
    a3.y += __shfl_xor_sync(0xffffffffu, a3.y, 16);
    a3.z += __shfl_xor_sync(0xffffffffu, a3.z, 16);
    a3.w += __shfl_xor_sync(0xffffffffu, a3.w, 16);

    int slot = p * NSPLIT + s;
    if (h == 0) {
        float4* pa = reinterpret_cast<float4*>(g_pacc + (size_t)slot * DIM);
        pa[i] = a0; pa[i + 16] = a1; pa[i + 32] = a2; pa[i + 48] = a3;
    }
    if (lane == 0) g_ps[slot] = ssum;
}

// ---------- L3: combine partials + residual (float4, 64 threads/point) ----------
__global__ void __launch_bounds__(64) k_combine(const float* __restrict__ pf,
                                                float* __restrict__ out) {
    int p = blockIdx.x;
    int t = threadIdx.x;   // 64 threads, each owns 4 dims
    float4 num = make_float4(0.f, 0.f, 0.f, 0.f);
    float den = 0.f;
    const float4* pa = reinterpret_cast<const float4*>(g_pacc + (size_t)p * NSPLIT * DIM);
    #pragma unroll 8
    for (int s = 0; s < NSPLIT; s++) {
        den += g_ps[p * NSPLIT + s];
        float4 v = pa[s * 64 + t];
        num.x += v.x; num.y += v.y; num.z += v.z; num.w += v.w;
    }
    float inv = (den > 0.f) ? (1.f / den) : 0.f;
    float4 base = reinterpret_cast<const float4*>(pf)[p * 64 + t];
    reinterpret_cast<float4*>(out)[p * 64 + t] =
        make_float4(base.x + num.x * inv, base.y + num.y * inv,
                    base.z + num.z * inv, base.w + num.w * inv);
}

extern "C" void kernel_launch(void* const* d_in, const int* in_sizes, int n_in,
                              void* d_out, int out_size) {
    const float* points_feat = (const float*)d_in[0];
    const float* box_feat    = (const float*)d_in[1];
    const float* centers     = (const float*)d_in[2];
    const float* boxes       = (const float*)d_in[3];
    const float* Wq          = (const float*)d_in[4];
    const float* bq          = (const float*)d_in[5];
    const float* Wk          = (const float*)d_in[6];
    const float* bk          = (const float*)d_in[7];
    const float* scales      = (const float*)d_in[8];
    float* out = (float*)d_out;

    k_misc<<<833, 256>>>(Wk, centers, scales, boxes,
                         points_feat, Wq, bq, bk);     // launch 0
    k_t<<<NPTS / 2, 256>>>(0);                         // launch 1
    dim3 agrid(NGROUP, NSPLIT);
    k_attn<<<agrid, 256>>>(box_feat, boxes);           // launch 2
    k_combine<<<NPTS, 64>>>(points_feat, out);         // launch 3
}